// round 14
// baseline (speedup 1.0000x reference)
#include <cuda_runtime.h>
#include <cuda_fp16.h>
#include <cstdint>

#define NN 100000
#define EE 1600000
#define HH 128
#define GG 512
#define CC 10
#define LH 384   // L*H
#define EPSV 1e-5f
#define NBLK 98  // ceil(NN/1024)

// ---------------- device scratch (no allocations allowed) ----------------
// zero-invariants: g_cnt, g_stat are zero at entry of every call
__device__ __align__(16) __half g_hW16[NN * HH]; // GEMM output, fp16 (dinv-scaled)
__device__ __align__(16) __half g_aggA[NN * HH]; // aggregation ping (fp16)
__device__ __align__(16) __half g_aggB[NN * HH]; // aggregation pong (fp16)
__device__ __align__(16) __half g_Wt16[3 * HH * HH]; // per-layer W, fp16, transposed [n][k]
__device__ float g_dinv[NN];
__device__ int   g_cnt[NN];
__device__ int   g_off[NN + 1];
__device__ int   g_cursor[NN];
__device__ int   g_srcA[EE];
__device__ int   g_bsum[128];
__device__ float g_stat[2 * HH];       // [0:128) sum, [128:256) sumsq
__device__ float g_meanL[3 * HH];      // per-layer BN stats
__device__ float g_istdL[3 * HH];
__device__ int   g_goff[GG + 1];
__device__ float g_pool[GG * LH];
__device__ float g_z[GG * HH];
__device__ float g_m2[HH];
__device__ float g_i2[HH];

// ---------------- setup kernels ----------------
__global__ void k_count(const int* __restrict__ dst) {
    int e = blockIdx.x * blockDim.x + threadIdx.x;
    if (e < EE) atomicAdd(&g_cnt[dst[e]], 1);
}

// block-local exclusive scan + block sums; writes dinv; ALSO converts+transposes W->fp16
__global__ void s_partial(const float* __restrict__ W1, const float* __restrict__ Wc) {
    __shared__ int wsum[32];
    int tid = threadIdx.x, lane = tid & 31, wid = tid >> 5;
    int idx = blockIdx.x * 1024 + tid;

    // W prep: 3 layers x 16384 elements = 49152 <= 98*1024
    if (idx < 3 * HH * HH) {
        int layer = idx >> 14;
        int e = idx & 16383;
        int k = e >> 7, n = e & 127;     // read coalesced over n
        const float* Wsrc = (layer == 0) ? W1 : (Wc + (layer - 1) * HH * HH);
        g_Wt16[layer * HH * HH + n * HH + k] = __float2half_rn(Wsrc[k * HH + n]);
    }

    int v = (idx < NN) ? g_cnt[idx] : 0;
    if (idx < NN) g_dinv[idx] = rsqrtf((float)(v + 1));
    int x = v;
    #pragma unroll
    for (int o = 1; o < 32; o <<= 1) {
        int y = __shfl_up_sync(0xffffffffu, x, o);
        if (lane >= o) x += y;
    }
    if (lane == 31) wsum[wid] = x;
    __syncthreads();
    if (wid == 0) {
        int w = wsum[lane];
        int xx = w;
        #pragma unroll
        for (int o = 1; o < 32; o <<= 1) {
            int y = __shfl_up_sync(0xffffffffu, xx, o);
            if (lane >= o) xx += y;
        }
        wsum[lane] = xx - w;
    }
    __syncthreads();
    int incl = x + wsum[wid];
    if (idx < NN) g_off[idx] = incl - v;     // block-local exclusive
    if (tid == 1023) g_bsum[blockIdx.x] = incl;
}

// finalize offsets, init cursor, zero g_cnt, graph offsets via boundary scan
__global__ void s_add(const int* __restrict__ batch) {
    __shared__ int sb[128];
    int tid = threadIdx.x;
    if (tid < 128) sb[tid] = (tid < NBLK) ? g_bsum[tid] : 0;
    __syncthreads();
    #pragma unroll
    for (int o = 1; o < 128; o <<= 1) {
        int v = 0;
        if (tid < 128 && tid >= o) v = sb[tid - o];
        __syncthreads();
        if (tid < 128) sb[tid] += v;
        __syncthreads();
    }
    int bpre = (blockIdx.x > 0) ? sb[blockIdx.x - 1] : 0;
    int idx = blockIdx.x * 1024 + tid;
    if (idx < NN) {
        int off = g_off[idx] + bpre;
        g_off[idx] = off;
        g_cursor[idx] = off;
        g_cnt[idx] = 0;                      // restore zero-invariant
        int b = batch[idx];
        int prev = (idx > 0) ? batch[idx - 1] : -1;
        for (int g = prev + 1; g <= b; g++) g_goff[g] = idx;
        if (idx == NN - 1)
            for (int g = b + 1; g <= GG; g++) g_goff[g] = NN;
    }
    if (idx == 0) g_off[NN] = EE;
}

__global__ void k_fill(const int* __restrict__ src, const int* __restrict__ dst) {
    int e = blockIdx.x * blockDim.x + threadIdx.x;
    if (e < EE) {
        int d = dst[e];
        int p = atomicAdd(&g_cursor[d], 1);
        g_srcA[p] = src[e];
    }
}

// ---------------- fp16 tensor-core GEMM (m16n8k16, fp32 accumulate) ----------------
__device__ __forceinline__ void mma_f16(float& c0, float& c1, float& c2, float& c3,
                                        uint32_t a0, uint32_t a1, uint32_t a2, uint32_t a3,
                                        uint32_t b0, uint32_t b1) {
    asm volatile("mma.sync.aligned.m16n8k16.row.col.f32.f16.f16.f32 "
                 "{%0,%1,%2,%3},{%4,%5,%6,%7},{%8,%9},{%0,%1,%2,%3};"
                 : "+f"(c0), "+f"(c1), "+f"(c2), "+f"(c3)
                 : "r"(a0), "r"(a1), "r"(a2), "r"(a3), "r"(b0), "r"(b1));
}

// generic 4-element load -> float4
__device__ __forceinline__ float4 load4(const float* p) { return *(const float4*)p; }
__device__ __forceinline__ float4 load4(const __half* p) {
    uint2 u = *(const uint2*)p;
    float2 lo = __half22float2(*(const __half2*)&u.x);
    float2 hi = __half22float2(*(const __half2*)&u.y);
    return make_float4(lo.x, lo.y, hi.x, hi.y);
}

#define SPAD 136  // smem row stride in halves: frag banks 4*gid+tig, conflict-free
#define SMEM_SB_BYTES (64 * SPAD * 2)               // 17408 (64 n-rows)
#define SMEM_SA_OFF   SMEM_SB_BYTES
#define SMEM_SA_BYTES (128 * SPAD * 2)              // 34816
#define SMEM_SC_OFF   (SMEM_SB_BYTES + SMEM_SA_BYTES)
#define SMEM_GEMM     (SMEM_SC_OFF + 1024)          // ~53.2KB dynamic smem

// C16 tile [128 x 64]: grid (782, 2). Wt fp16 pre-transposed [n][k].
template <typename TA>
__global__ __launch_bounds__(256, 3) void k_gemm_h(const TA* __restrict__ A,
                                                   const __half* __restrict__ Wt,
                                                   __half* __restrict__ C16,
                                                   int doBN, int statLayer,
                                                   const float* __restrict__ gamma,
                                                   const float* __restrict__ beta) {
    extern __shared__ __align__(16) char smem[];
    __half (*sB)[SPAD] = (__half(*)[SPAD])(smem);                 // [n-local][k]
    __half (*sA)[SPAD] = (__half(*)[SPAD])(smem + SMEM_SA_OFF);   // [row][k]
    float* sScale = (float*)(smem + SMEM_SC_OFF);
    float* sShift = sScale + HH;

    int tid = threadIdx.x;
    int nbase = blockIdx.y * 64;
    if (doBN && tid < HH) {
        float is = g_istdL[statLayer * HH + tid] * gamma[tid];
        sScale[tid] = is;
        sShift[tid] = beta[tid] - g_meanL[statLayer * HH + tid] * is;
    }

    // stage W slice [64 n x 128 k] from fp16 pre-transposed Wt (vectorized, coalesced)
    #pragma unroll
    for (int i = 0; i < 8; i++) {
        int idx = i * 256 + tid;          // 2048 packs of 4 k-values
        int n  = idx >> 5;                // 0..63
        int k0 = (idx & 31) * 4;          // 0..124 (consecutive threads -> contiguous)
        *(uint2*)&sB[n][k0] = *(const uint2*)(Wt + (size_t)(nbase + n) * HH + k0);
    }
    __syncthreads();   // orders sScale/sShift writes before A-staging reads

    int rowBase = blockIdx.x * 128;

    // stage full A tile [128 x 128] (BN+ReLU fused), fp16
    #pragma unroll
    for (int i = 0; i < 16; i++) {
        int v = i * 256 + tid;
        int row = v & 127;
        int k0 = (v >> 7) * 4;            // 0..124
        int gr = rowBase + row;
        float4 a4 = make_float4(0.f, 0.f, 0.f, 0.f);
        if (gr < NN) a4 = load4(A + (size_t)gr * HH + k0);
        if (doBN) {
            a4.x = fmaxf(0.f, fmaf(a4.x, sScale[k0], sShift[k0]));
            a4.y = fmaxf(0.f, fmaf(a4.y, sScale[k0 + 1], sShift[k0 + 1]));
            a4.z = fmaxf(0.f, fmaf(a4.z, sScale[k0 + 2], sShift[k0 + 2]));
            a4.w = fmaxf(0.f, fmaf(a4.w, sScale[k0 + 3], sShift[k0 + 3]));
        }
        __half2 h01 = __floats2half2_rn(a4.x, a4.y);
        __half2 h23 = __floats2half2_rn(a4.z, a4.w);
        uint2 pk = make_uint2(*(uint32_t*)&h01, *(uint32_t*)&h23);
        *(uint2*)&sA[row][k0] = pk;
    }
    __syncthreads();

    int lane = tid & 31, wid = tid >> 5;
    int gid = lane >> 2, tig = lane & 3;
    int warp_m = wid & 3, warp_n = wid >> 2;     // 4 x 2 warp grid over 128x64
    int mrow = warp_m * 32;
    int ncol0 = warp_n * 32;

    float acc[2][4][4];
    #pragma unroll
    for (int mt = 0; mt < 2; mt++)
        #pragma unroll
        for (int nt = 0; nt < 4; nt++)
            #pragma unroll
            for (int r = 0; r < 4; r++) acc[mt][nt][r] = 0.f;

    #pragma unroll
    for (int ks = 0; ks < 8; ks++) {
        int kg = ks * 16;
        uint32_t a[2][4];
        #pragma unroll
        for (int mt = 0; mt < 2; mt++) {
            int m0 = mrow + mt * 16 + gid;
            a[mt][0] = *(const uint32_t*)&sA[m0][kg + 2 * tig];
            a[mt][1] = *(const uint32_t*)&sA[m0 + 8][kg + 2 * tig];
            a[mt][2] = *(const uint32_t*)&sA[m0][kg + 2 * tig + 8];
            a[mt][3] = *(const uint32_t*)&sA[m0 + 8][kg + 2 * tig + 8];
        }
        #pragma unroll
        for (int nt = 0; nt < 4; nt++) {
            int nc = ncol0 + nt * 8 + gid;
            uint32_t b0 = *(const uint32_t*)&sB[nc][kg + 2 * tig];
            uint32_t b1 = *(const uint32_t*)&sB[nc][kg + 2 * tig + 8];
            #pragma unroll
            for (int mt = 0; mt < 2; mt++) {
                float* c = acc[mt][nt];
                mma_f16(c[0], c[1], c[2], c[3],
                        a[mt][0], a[mt][1], a[mt][2], a[mt][3], b0, b1);
            }
        }
    }

    // epilogue: scale by dinv[row], convert fp16, write
    #pragma unroll
    for (int mt = 0; mt < 2; mt++) {
        int r0 = rowBase + mrow + mt * 16 + gid;
        int r1 = r0 + 8;
        float dv0 = (r0 < NN) ? g_dinv[r0] : 0.f;
        float dv1 = (r1 < NN) ? g_dinv[r1] : 0.f;
        #pragma unroll
        for (int nt = 0; nt < 4; nt++) {
            int c = nbase + ncol0 + nt * 8 + 2 * tig;
            float* a2 = acc[mt][nt];
            if (r0 < NN) *(__half2*)(C16 + (size_t)r0 * HH + c) = __floats2half2_rn(a2[0] * dv0, a2[1] * dv0);
            if (r1 < NN) *(__half2*)(C16 + (size_t)r1 * HH + c) = __floats2half2_rn(a2[2] * dv1, a2[3] * dv1);
        }
    }
}

// ---------------- aggregation: software-pipelined CSR gather + BN stats ----------------
// out[d] = dinv[d] * ( sum_{s in N(d)} hs[s] + hs[d] ),  hs = g_hW16 (dinv-scaled fp16)
#define AGG_GATHER(dst4, sidx) \
    { uint2 _r = *(const uint2*)(hw + (size_t)(sidx) * HH + col); dst4 = _r; }
#define AGG_ACC(r) \
    { float2 _a = __half22float2(*(__half2*)&(r).x); \
      float2 _b = __half22float2(*(__half2*)&(r).y); \
      ax += _a.x; ay += _a.y; az += _b.x; aw += _b.y; }

__global__ __launch_bounds__(256) void k_agg(const __half* __restrict__ hw,
                                             __half* __restrict__ out) {
    __shared__ float s_sum[HH], s_sq[HH];
    int tid = threadIdx.x;
    if (tid < HH) { s_sum[tid] = 0.f; s_sq[tid] = 0.f; }
    __syncthreads();
    int lane = tid & 31;
    int col = lane * 4;   // 4 halves (= 1 uint2) per lane, 32 lanes = 128 cols
    int gw = (blockIdx.x * blockDim.x + tid) >> 5;
    int nw = (gridDim.x * blockDim.x) >> 5;
    float lsx = 0.f, lsy = 0.f, lsz = 0.f, lsw = 0.f;
    float lqx = 0.f, lqy = 0.f, lqz = 0.f, lqw = 0.f;
    for (int node = gw; node < NN; node += nw) {
        uint2 rv;
        AGG_GATHER(rv, node);
        float2 f0 = __half22float2(*(__half2*)&rv.x);
        float2 f1 = __half22float2(*(__half2*)&rv.y);
        float ax = f0.x, ay = f0.y, az = f1.x, aw = f1.y;
        int e0 = __ldg(&g_off[node]), e1 = __ldg(&g_off[node + 1]);
        int deg = e1 - e0;
        int nf = deg >> 2;             // number of full 4-edge groups
        if (nf >= 2) {
            int s0 = __ldg(&g_srcA[e0]),     s1 = __ldg(&g_srcA[e0 + 1]);
            int s2 = __ldg(&g_srcA[e0 + 2]), s3 = __ldg(&g_srcA[e0 + 3]);
            uint2 p0, p1, p2, p3;
            AGG_GATHER(p0, s0); AGG_GATHER(p1, s1); AGG_GATHER(p2, s2); AGG_GATHER(p3, s3);
            int t0 = __ldg(&g_srcA[e0 + 4]), t1 = __ldg(&g_srcA[e0 + 5]);
            int t2 = __ldg(&g_srcA[e0 + 6]), t3 = __ldg(&g_srcA[e0 + 7]);
            int e = e0 + 8;
            int iters = nf - 2;
            while (iters > 0) {
                uint2 q0, q1, q2, q3;
                AGG_GATHER(q0, t0); AGG_GATHER(q1, t1); AGG_GATHER(q2, t2); AGG_GATHER(q3, t3);
                t0 = __ldg(&g_srcA[e]);     t1 = __ldg(&g_srcA[e + 1]);
                t2 = __ldg(&g_srcA[e + 2]); t3 = __ldg(&g_srcA[e + 3]);
                AGG_ACC(p0); AGG_ACC(p1); AGG_ACC(p2); AGG_ACC(p3);
                p0 = q0; p1 = q1; p2 = q2; p3 = q3;
                e += 4; iters--;
            }
            uint2 q0, q1, q2, q3;
            AGG_GATHER(q0, t0); AGG_GATHER(q1, t1); AGG_GATHER(q2, t2); AGG_GATHER(q3, t3);
            AGG_ACC(p0); AGG_ACC(p1); AGG_ACC(p2); AGG_ACC(p3);
            AGG_ACC(q0); AGG_ACC(q1); AGG_ACC(q2); AGG_ACC(q3);
        } else if (nf == 1) {
            int s0 = __ldg(&g_srcA[e0]),     s1 = __ldg(&g_srcA[e0 + 1]);
            int s2 = __ldg(&g_srcA[e0 + 2]), s3 = __ldg(&g_srcA[e0 + 3]);
            uint2 p0, p1, p2, p3;
            AGG_GATHER(p0, s0); AGG_GATHER(p1, s1); AGG_GATHER(p2, s2); AGG_GATHER(p3, s3);
            AGG_ACC(p0); AGG_ACC(p1); AGG_ACC(p2); AGG_ACC(p3);
        }
        for (int e = e0 + (nf << 2); e < e1; e++) {
            int s0 = __ldg(&g_srcA[e]);
            uint2 r0;
            AGG_GATHER(r0, s0);
            AGG_ACC(r0);
        }
        float dv = g_dinv[node];
        ax *= dv; ay *= dv; az *= dv; aw *= dv;
        __half2 o01 = __floats2half2_rn(ax, ay);
        __half2 o23 = __floats2half2_rn(az, aw);
        uint2 ov = make_uint2(*(uint32_t*)&o01, *(uint32_t*)&o23);
        *(uint2*)(out + (size_t)node * HH + col) = ov;
        lsx += ax; lsy += ay; lsz += az; lsw += aw;
        lqx += ax * ax; lqy += ay * ay; lqz += az * az; lqw += aw * aw;
    }
    atomicAdd(&s_sum[col], lsx);     atomicAdd(&s_sum[col + 1], lsy);
    atomicAdd(&s_sum[col + 2], lsz); atomicAdd(&s_sum[col + 3], lsw);
    atomicAdd(&s_sq[col], lqx);      atomicAdd(&s_sq[col + 1], lqy);
    atomicAdd(&s_sq[col + 2], lqz);  atomicAdd(&s_sq[col + 3], lqw);
    __syncthreads();
    if (tid < HH) {
        atomicAdd(&g_stat[tid], s_sum[tid]);
        atomicAdd(&g_stat[HH + tid], s_sq[tid]);
    }
}

__global__ void k_fin(int layer) {  // finalize layer BN stats, re-zero g_stat
    int t = threadIdx.x;
    if (t < HH) {
        float m = g_stat[t] * (1.f / NN);
        float v = g_stat[HH + t] * (1.f / NN) - m * m;
        g_meanL[layer * HH + t] = m;
        g_istdL[layer * HH + t] = rsqrtf(v + EPSV);
        g_stat[t] = 0.f;
        g_stat[HH + t] = 0.f;
    }
}

// per-graph mean pool with fused BN+ReLU (fp16 activations)
__global__ void k_pool(const __half* __restrict__ agg,
                       const float* __restrict__ gamma,
                       const float* __restrict__ beta, int layer) {
    int g = blockIdx.x, c = threadIdx.x;
    int b = g_goff[g], e = g_goff[g + 1];
    float is = g_istdL[layer * HH + c] * gamma[c];
    float sh = beta[c] - g_meanL[layer * HH + c] * is;
    float s = 0.f;
    for (int r = b; r < e; r++) {
        float x = __half2float(agg[(size_t)r * HH + c]);
        s += fmaxf(0.f, fmaf(x, is, sh));
    }
    int n = e - b;
    float cnt = (float)(n > 1 ? n : 1);
    g_pool[g * LH + layer * HH + c] = s / cnt;
}

// ---------------- MLP head ----------------
__global__ void k_lin1(const float* __restrict__ Wl1, const float* __restrict__ bl1) {
    __shared__ float sp[LH];
    int g = blockIdx.x, t = threadIdx.x;
    sp[t]       = g_pool[g * LH + t];
    sp[t + 128] = g_pool[g * LH + t + 128];
    sp[t + 256] = g_pool[g * LH + t + 256];
    __syncthreads();
    float a = bl1[t];
    #pragma unroll 4
    for (int k = 0; k < LH; k++) a = fmaf(sp[k], Wl1[k * HH + t], a);
    g_z[g * HH + t] = a;
}

__global__ void k_bn2() {
    int t = threadIdx.x;
    if (t < HH) {
        float s = 0.f, q = 0.f;
        for (int r = 0; r < GG; r++) {
            float x = g_z[r * HH + t];
            s += x; q += x * x;
        }
        float m = s * (1.f / GG);
        float v = q * (1.f / GG) - m * m;
        g_m2[t] = m;
        g_i2[t] = rsqrtf(v + EPSV);
    }
}

__global__ void k_final(const float* __restrict__ gl, const float* __restrict__ btl,
                        const float* __restrict__ Wl2, const float* __restrict__ bl2,
                        float* __restrict__ out) {
    __shared__ float zr[HH];
    __shared__ float lg[CC];
    __shared__ float s_ls;
    int g = blockIdx.x, t = threadIdx.x;
    float x = g_z[g * HH + t];
    zr[t] = fmaxf(0.f, (x - g_m2[t]) * g_i2[t] * gl[t] + btl[t]);
    __syncthreads();
    if (t < CC) {
        float d = bl2[t];
        #pragma unroll 4
        for (int j = 0; j < HH; j++) d = fmaf(zr[j], Wl2[j * CC + t], d);
        lg[t] = d;
    }
    __syncthreads();
    if (t == 0) {
        float m = lg[0];
        for (int c = 1; c < CC; c++) m = fmaxf(m, lg[c]);
        float se = 0.f;
        for (int c = 0; c < CC; c++) se += expf(lg[c] - m);
        s_ls = m + logf(se);
    }
    __syncthreads();
    if (t < CC) out[g * CC + t] = lg[t] - s_ls;
}

// ---------------- launch (single serial stream) ----------------
extern "C" void kernel_launch(void* const* d_in, const int* in_sizes, int n_in,
                              void* d_out, int out_size) {
    const float* x     = (const float*)d_in[0];
    const int*   ei    = (const int*)d_in[1];     // int32 (JAX x64 disabled)
    const int*   batch = (const int*)d_in[2];
    const float* W1  = (const float*)d_in[3];
    const float* g1  = (const float*)d_in[5];
    const float* bt1 = (const float*)d_in[6];
    const float* Wc  = (const float*)d_in[7];
    const float* gc  = (const float*)d_in[9];
    const float* btc = (const float*)d_in[10];
    const float* Wl1 = (const float*)d_in[11];
    const float* bl1 = (const float*)d_in[12];
    const float* gl  = (const float*)d_in[13];
    const float* btl = (const float*)d_in[14];
    const float* Wl2 = (const float*)d_in[15];
    const float* bl2 = (const float*)d_in[16];
    const int* src = ei;
    const int* dst = ei + EE;

    void *p_hW, *p_aggA, *p_aggB, *p_Wt;
    cudaGetSymbolAddress(&p_hW, g_hW16);
    cudaGetSymbolAddress(&p_aggA, g_aggA);
    cudaGetSymbolAddress(&p_aggB, g_aggB);
    cudaGetSymbolAddress(&p_Wt, g_Wt16);
    __half* hW   = (__half*)p_hW;
    __half* aggA = (__half*)p_aggA;
    __half* aggB = (__half*)p_aggB;
    __half* Wt   = (__half*)p_Wt;

    cudaFuncSetAttribute(k_gemm_h<float>,  cudaFuncAttributeMaxDynamicSharedMemorySize, SMEM_GEMM);
    cudaFuncSetAttribute(k_gemm_h<__half>, cudaFuncAttributeMaxDynamicSharedMemorySize, SMEM_GEMM);

    dim3 GEMM_GRID((NN + 127) / 128, 2);
    const int AGG_GRID = 1480;

    // ---- setup; kernel #4 (profiled) is k_gemm_h ----
    k_count<<<(EE + 255) / 256, 256>>>(dst);          // 1
    s_partial<<<NBLK, 1024>>>(W1, Wc);                // 2 (dinv + W fp16 transpose)
    s_add<<<NBLK, 1024>>>(batch);                     // 3
    k_gemm_h<float><<<GEMM_GRID, 256, SMEM_GEMM>>>(x, Wt, hW, 0, 0, (const float*)0, (const float*)0); // 4 (profiled)
    k_fill<<<(EE + 255) / 256, 256>>>(src, dst);      // 5

    // ---- layer 0 ----
    k_agg<<<AGG_GRID, 256>>>(hW, aggA);
    k_fin<<<1, 128>>>(0);
    k_pool<<<GG, 128>>>(aggA, g1, bt1, 0);

    // ---- layer 1: BN0(aggA) -> aggB ----
    k_gemm_h<__half><<<GEMM_GRID, 256, SMEM_GEMM>>>(aggA, Wt + HH * HH, hW, 1, 0, g1, bt1);
    k_agg<<<AGG_GRID, 256>>>(hW, aggB);
    k_fin<<<1, 128>>>(1);
    k_pool<<<GG, 128>>>(aggB, gc, btc, 1);

    // ---- layer 2: BN1(aggB) -> aggA ----
    k_gemm_h<__half><<<GEMM_GRID, 256, SMEM_GEMM>>>(aggB, Wt + 2 * HH * HH, hW, 1, 1, gc, btc);
    k_agg<<<AGG_GRID, 256>>>(hW, aggA);
    k_fin<<<1, 128>>>(2);
    k_pool<<<GG, 128>>>(aggA, gc + HH, btc + HH, 2);

    // ---- head ----
    k_lin1<<<GG, 128>>>(Wl1, bl1);
    k_bn2<<<1, 128>>>();
    k_final<<<GG, 128>>>(gl, btl, Wl2, bl2, (float*)d_out);
}

// round 15
// speedup vs baseline: 1.0749x; 1.0749x over previous
#include <cuda_runtime.h>
#include <cuda_fp16.h>
#include <cstdint>

#define NN 100000
#define EE 1600000
#define HH 128
#define GG 512
#define CC 10
#define LH 384   // L*H
#define EPSV 1e-5f
#define NBLK 98  // ceil(NN/1024)

// ---------------- device scratch (no allocations allowed) ----------------
// zero-invariants: g_cnt, g_stat are zero at entry of every call
__device__ __align__(16) __half g_hW16[NN * HH]; // GEMM output, fp16 (dinv-scaled)
__device__ __align__(16) __half g_aggA[NN * HH]; // aggregation ping (fp16)
__device__ __align__(16) __half g_aggB[NN * HH]; // aggregation pong (fp16)
__device__ __align__(16) __half g_Wt16[3 * HH * HH]; // per-layer W, fp16, transposed [n][k]
__device__ float g_dinv[NN];
__device__ int   g_cnt[NN];
__device__ int   g_off[NN + 1];
__device__ int   g_cursor[NN];
__device__ int   g_srcA[EE];
__device__ int   g_bsum[128];
__device__ float g_stat[2 * HH];       // [0:128) sum, [128:256) sumsq
__device__ float g_meanL[3 * HH];      // per-layer BN stats
__device__ float g_istdL[3 * HH];
__device__ int   g_goff[GG + 1];
__device__ float g_pool[GG * LH];
__device__ float g_z[GG * HH];
__device__ float g_m2[HH];
__device__ float g_i2[HH];

// ---------------- setup kernels ----------------
__global__ void k_count(const int* __restrict__ dst) {
    int e = blockIdx.x * blockDim.x + threadIdx.x;
    if (e < EE) atomicAdd(&g_cnt[dst[e]], 1);
}

// block-local exclusive scan + block sums; writes dinv; ALSO converts+transposes W->fp16
__global__ void s_partial(const float* __restrict__ W1, const float* __restrict__ Wc) {
    __shared__ int wsum[32];
    int tid = threadIdx.x, lane = tid & 31, wid = tid >> 5;
    int idx = blockIdx.x * 1024 + tid;

    // W prep: 3 layers x 16384 elements = 49152 <= 98*1024
    if (idx < 3 * HH * HH) {
        int layer = idx >> 14;
        int e = idx & 16383;
        int k = e >> 7, n = e & 127;     // read coalesced over n
        const float* Wsrc = (layer == 0) ? W1 : (Wc + (layer - 1) * HH * HH);
        g_Wt16[layer * HH * HH + n * HH + k] = __float2half_rn(Wsrc[k * HH + n]);
    }

    int v = (idx < NN) ? g_cnt[idx] : 0;
    if (idx < NN) g_dinv[idx] = rsqrtf((float)(v + 1));
    int x = v;
    #pragma unroll
    for (int o = 1; o < 32; o <<= 1) {
        int y = __shfl_up_sync(0xffffffffu, x, o);
        if (lane >= o) x += y;
    }
    if (lane == 31) wsum[wid] = x;
    __syncthreads();
    if (wid == 0) {
        int w = wsum[lane];
        int xx = w;
        #pragma unroll
        for (int o = 1; o < 32; o <<= 1) {
            int y = __shfl_up_sync(0xffffffffu, xx, o);
            if (lane >= o) xx += y;
        }
        wsum[lane] = xx - w;
    }
    __syncthreads();
    int incl = x + wsum[wid];
    if (idx < NN) g_off[idx] = incl - v;     // block-local exclusive
    if (tid == 1023) g_bsum[blockIdx.x] = incl;
}

// finalize offsets, init cursor, zero g_cnt, graph offsets via boundary scan
__global__ void s_add(const int* __restrict__ batch) {
    __shared__ int sb[128];
    int tid = threadIdx.x;
    if (tid < 128) sb[tid] = (tid < NBLK) ? g_bsum[tid] : 0;
    __syncthreads();
    #pragma unroll
    for (int o = 1; o < 128; o <<= 1) {
        int v = 0;
        if (tid < 128 && tid >= o) v = sb[tid - o];
        __syncthreads();
        if (tid < 128) sb[tid] += v;
        __syncthreads();
    }
    int bpre = (blockIdx.x > 0) ? sb[blockIdx.x - 1] : 0;
    int idx = blockIdx.x * 1024 + tid;
    if (idx < NN) {
        int off = g_off[idx] + bpre;
        g_off[idx] = off;
        g_cursor[idx] = off;
        g_cnt[idx] = 0;                      // restore zero-invariant
        int b = batch[idx];
        int prev = (idx > 0) ? batch[idx - 1] : -1;
        for (int g = prev + 1; g <= b; g++) g_goff[g] = idx;
        if (idx == NN - 1)
            for (int g = b + 1; g <= GG; g++) g_goff[g] = NN;
    }
    if (idx == 0) g_off[NN] = EE;
}

__global__ void k_fill(const int* __restrict__ src, const int* __restrict__ dst) {
    int e = blockIdx.x * blockDim.x + threadIdx.x;
    if (e < EE) {
        int d = dst[e];
        int p = atomicAdd(&g_cursor[d], 1);
        g_srcA[p] = src[e];
    }
}

// ---------------- fp16 tensor-core GEMM (m16n8k16, fp32 accumulate) ----------------
__device__ __forceinline__ void mma_f16(float& c0, float& c1, float& c2, float& c3,
                                        uint32_t a0, uint32_t a1, uint32_t a2, uint32_t a3,
                                        uint32_t b0, uint32_t b1) {
    asm volatile("mma.sync.aligned.m16n8k16.row.col.f32.f16.f16.f32 "
                 "{%0,%1,%2,%3},{%4,%5,%6,%7},{%8,%9},{%0,%1,%2,%3};"
                 : "+f"(c0), "+f"(c1), "+f"(c2), "+f"(c3)
                 : "r"(a0), "r"(a1), "r"(a2), "r"(a3), "r"(b0), "r"(b1));
}

// generic 4-element load -> float4
__device__ __forceinline__ float4 load4(const float* p) { return *(const float4*)p; }
__device__ __forceinline__ float4 load4(const __half* p) {
    uint2 u = *(const uint2*)p;
    float2 lo = __half22float2(*(const __half2*)&u.x);
    float2 hi = __half22float2(*(const __half2*)&u.y);
    return make_float4(lo.x, lo.y, hi.x, hi.y);
}

#define SPAD 136  // smem row stride in halves (68 words): frag banks 4*gid+tig, conflict-free
#define SMEM_SB_BYTES (128 * SPAD * 2)              // 34816
#define SMEM_SA_OFF   SMEM_SB_BYTES
#define SMEM_SC_OFF   (2 * SMEM_SB_BYTES)           // 69632
#define SMEM_GEMM     (SMEM_SC_OFF + 1024)          // 70656 total dynamic smem

// C16[N,128] = fp16( dinv[row] * (relu(BN_layer(A))[N,128] @ W[128,128]) )
// Full W (fp16 pre-transposed) + full A tile staged once; 2 syncs/CTA, 8-step MMA block.
template <typename TA>
__global__ __launch_bounds__(256, 2) void k_gemm_h(const TA* __restrict__ A,
                                                   const __half* __restrict__ Wt,
                                                   __half* __restrict__ C16,
                                                   int doBN, int statLayer,
                                                   const float* __restrict__ gamma,
                                                   const float* __restrict__ beta) {
    extern __shared__ __align__(16) char smem[];
    __half (*sB)[SPAD] = (__half(*)[SPAD])(smem);                 // [n][k]
    __half (*sA)[SPAD] = (__half(*)[SPAD])(smem + SMEM_SA_OFF);   // [row][k]
    float* sScale = (float*)(smem + SMEM_SC_OFF);
    float* sShift = sScale + HH;

    int tid = threadIdx.x;
    if (doBN && tid < HH) {
        float is = g_istdL[statLayer * HH + tid] * gamma[tid];
        sScale[tid] = is;
        sShift[tid] = beta[tid] - g_meanL[statLayer * HH + tid] * is;
    }

    // stage full W slice from fp16 pre-transposed Wt (vectorized, coalesced)
    #pragma unroll
    for (int i = 0; i < 16; i++) {
        int idx = i * 256 + tid;          // 4096 packs of 4 k-values
        int n  = idx >> 5;                // 0..127
        int k0 = (idx & 31) * 4;          // 0..124 (consecutive threads contiguous)
        *(uint2*)&sB[n][k0] = *(const uint2*)(Wt + (size_t)n * HH + k0);
    }
    __syncthreads();   // orders sScale/sShift writes before A-staging reads

    int rowBase = blockIdx.x * 128;

    // stage full A tile [128 x 128] (BN+ReLU fused), fp16 — 16 packs/thread, MLP-heavy
    #pragma unroll
    for (int i = 0; i < 16; i++) {
        int v = i * 256 + tid;
        int row = v & 127;
        int k0 = (v >> 7) * 4;            // 0..124
        int gr = rowBase + row;
        float4 a4 = make_float4(0.f, 0.f, 0.f, 0.f);
        if (gr < NN) a4 = load4(A + (size_t)gr * HH + k0);
        if (doBN) {
            a4.x = fmaxf(0.f, fmaf(a4.x, sScale[k0], sShift[k0]));
            a4.y = fmaxf(0.f, fmaf(a4.y, sScale[k0 + 1], sShift[k0 + 1]));
            a4.z = fmaxf(0.f, fmaf(a4.z, sScale[k0 + 2], sShift[k0 + 2]));
            a4.w = fmaxf(0.f, fmaf(a4.w, sScale[k0 + 3], sShift[k0 + 3]));
        }
        __half2 h01 = __floats2half2_rn(a4.x, a4.y);
        __half2 h23 = __floats2half2_rn(a4.z, a4.w);
        uint2 pk = make_uint2(*(uint32_t*)&h01, *(uint32_t*)&h23);
        *(uint2*)&sA[row][k0] = pk;
    }
    __syncthreads();

    int lane = tid & 31, wid = tid >> 5;
    int gid = lane >> 2, tig = lane & 3;
    int warp_m = wid & 3, warp_n = wid >> 2;     // 4 x 2 warp grid
    int mrow = warp_m * 32;
    int ncol0 = warp_n * 64;

    float acc[2][8][4];
    #pragma unroll
    for (int mt = 0; mt < 2; mt++)
        #pragma unroll
        for (int nt = 0; nt < 8; nt++)
            #pragma unroll
            for (int r = 0; r < 4; r++) acc[mt][nt][r] = 0.f;

    #pragma unroll
    for (int ks = 0; ks < 8; ks++) {
        int kg = ks * 16;
        uint32_t a[2][4];
        #pragma unroll
        for (int mt = 0; mt < 2; mt++) {
            int m0 = mrow + mt * 16 + gid;
            a[mt][0] = *(const uint32_t*)&sA[m0][kg + 2 * tig];
            a[mt][1] = *(const uint32_t*)&sA[m0 + 8][kg + 2 * tig];
            a[mt][2] = *(const uint32_t*)&sA[m0][kg + 2 * tig + 8];
            a[mt][3] = *(const uint32_t*)&sA[m0 + 8][kg + 2 * tig + 8];
        }
        #pragma unroll
        for (int nt = 0; nt < 8; nt++) {
            int nc = ncol0 + nt * 8 + gid;
            uint32_t b0 = *(const uint32_t*)&sB[nc][kg + 2 * tig];
            uint32_t b1 = *(const uint32_t*)&sB[nc][kg + 2 * tig + 8];
            #pragma unroll
            for (int mt = 0; mt < 2; mt++) {
                float* c = acc[mt][nt];
                mma_f16(c[0], c[1], c[2], c[3],
                        a[mt][0], a[mt][1], a[mt][2], a[mt][3], b0, b1);
            }
        }
    }

    // epilogue: scale by dinv[row], convert fp16, write
    #pragma unroll
    for (int mt = 0; mt < 2; mt++) {
        int r0 = rowBase + mrow + mt * 16 + gid;
        int r1 = r0 + 8;
        float dv0 = (r0 < NN) ? g_dinv[r0] : 0.f;
        float dv1 = (r1 < NN) ? g_dinv[r1] : 0.f;
        #pragma unroll
        for (int nt = 0; nt < 8; nt++) {
            int c = ncol0 + nt * 8 + 2 * tig;
            float* a2 = acc[mt][nt];
            if (r0 < NN) *(__half2*)(C16 + (size_t)r0 * HH + c) = __floats2half2_rn(a2[0] * dv0, a2[1] * dv0);
            if (r1 < NN) *(__half2*)(C16 + (size_t)r1 * HH + c) = __floats2half2_rn(a2[2] * dv1, a2[3] * dv1);
        }
    }
}

// ---------------- aggregation: software-pipelined CSR gather + BN stats ----------------
// out[d] = dinv[d] * ( sum_{s in N(d)} hs[s] + hs[d] ),  hs = g_hW16 (dinv-scaled fp16)
#define AGG_GATHER(dst4, sidx) \
    { uint2 _r = *(const uint2*)(hw + (size_t)(sidx) * HH + col); dst4 = _r; }
#define AGG_ACC(r) \
    { float2 _a = __half22float2(*(__half2*)&(r).x); \
      float2 _b = __half22float2(*(__half2*)&(r).y); \
      ax += _a.x; ay += _a.y; az += _b.x; aw += _b.y; }

__global__ __launch_bounds__(256) void k_agg(const __half* __restrict__ hw,
                                             __half* __restrict__ out) {
    __shared__ float s_sum[HH], s_sq[HH];
    int tid = threadIdx.x;
    if (tid < HH) { s_sum[tid] = 0.f; s_sq[tid] = 0.f; }
    __syncthreads();
    int lane = tid & 31;
    int col = lane * 4;   // 4 halves (= 1 uint2) per lane, 32 lanes = 128 cols
    int gw = (blockIdx.x * blockDim.x + tid) >> 5;
    int nw = (gridDim.x * blockDim.x) >> 5;
    float lsx = 0.f, lsy = 0.f, lsz = 0.f, lsw = 0.f;
    float lqx = 0.f, lqy = 0.f, lqz = 0.f, lqw = 0.f;
    for (int node = gw; node < NN; node += nw) {
        uint2 rv;
        AGG_GATHER(rv, node);
        float2 f0 = __half22float2(*(__half2*)&rv.x);
        float2 f1 = __half22float2(*(__half2*)&rv.y);
        float ax = f0.x, ay = f0.y, az = f1.x, aw = f1.y;
        int e0 = __ldg(&g_off[node]), e1 = __ldg(&g_off[node + 1]);
        int deg = e1 - e0;
        int nf = deg >> 2;             // number of full 4-edge groups
        if (nf >= 2) {
            int s0 = __ldg(&g_srcA[e0]),     s1 = __ldg(&g_srcA[e0 + 1]);
            int s2 = __ldg(&g_srcA[e0 + 2]), s3 = __ldg(&g_srcA[e0 + 3]);
            uint2 p0, p1, p2, p3;
            AGG_GATHER(p0, s0); AGG_GATHER(p1, s1); AGG_GATHER(p2, s2); AGG_GATHER(p3, s3);
            int t0 = __ldg(&g_srcA[e0 + 4]), t1 = __ldg(&g_srcA[e0 + 5]);
            int t2 = __ldg(&g_srcA[e0 + 6]), t3 = __ldg(&g_srcA[e0 + 7]);
            int e = e0 + 8;
            int iters = nf - 2;
            while (iters > 0) {
                uint2 q0, q1, q2, q3;
                AGG_GATHER(q0, t0); AGG_GATHER(q1, t1); AGG_GATHER(q2, t2); AGG_GATHER(q3, t3);
                t0 = __ldg(&g_srcA[e]);     t1 = __ldg(&g_srcA[e + 1]);
                t2 = __ldg(&g_srcA[e + 2]); t3 = __ldg(&g_srcA[e + 3]);
                AGG_ACC(p0); AGG_ACC(p1); AGG_ACC(p2); AGG_ACC(p3);
                p0 = q0; p1 = q1; p2 = q2; p3 = q3;
                e += 4; iters--;
            }
            uint2 q0, q1, q2, q3;
            AGG_GATHER(q0, t0); AGG_GATHER(q1, t1); AGG_GATHER(q2, t2); AGG_GATHER(q3, t3);
            AGG_ACC(p0); AGG_ACC(p1); AGG_ACC(p2); AGG_ACC(p3);
            AGG_ACC(q0); AGG_ACC(q1); AGG_ACC(q2); AGG_ACC(q3);
        } else if (nf == 1) {
            int s0 = __ldg(&g_srcA[e0]),     s1 = __ldg(&g_srcA[e0 + 1]);
            int s2 = __ldg(&g_srcA[e0 + 2]), s3 = __ldg(&g_srcA[e0 + 3]);
            uint2 p0, p1, p2, p3;
            AGG_GATHER(p0, s0); AGG_GATHER(p1, s1); AGG_GATHER(p2, s2); AGG_GATHER(p3, s3);
            AGG_ACC(p0); AGG_ACC(p1); AGG_ACC(p2); AGG_ACC(p3);
        }
        for (int e = e0 + (nf << 2); e < e1; e++) {
            int s0 = __ldg(&g_srcA[e]);
            uint2 r0;
            AGG_GATHER(r0, s0);
            AGG_ACC(r0);
        }
        float dv = g_dinv[node];
        ax *= dv; ay *= dv; az *= dv; aw *= dv;
        __half2 o01 = __floats2half2_rn(ax, ay);
        __half2 o23 = __floats2half2_rn(az, aw);
        uint2 ov = make_uint2(*(uint32_t*)&o01, *(uint32_t*)&o23);
        *(uint2*)(out + (size_t)node * HH + col) = ov;
        lsx += ax; lsy += ay; lsz += az; lsw += aw;
        lqx += ax * ax; lqy += ay * ay; lqz += az * az; lqw += aw * aw;
    }
    atomicAdd(&s_sum[col], lsx);     atomicAdd(&s_sum[col + 1], lsy);
    atomicAdd(&s_sum[col + 2], lsz); atomicAdd(&s_sum[col + 3], lsw);
    atomicAdd(&s_sq[col], lqx);      atomicAdd(&s_sq[col + 1], lqy);
    atomicAdd(&s_sq[col + 2], lqz);  atomicAdd(&s_sq[col + 3], lqw);
    __syncthreads();
    if (tid < HH) {
        atomicAdd(&g_stat[tid], s_sum[tid]);
        atomicAdd(&g_stat[HH + tid], s_sq[tid]);
    }
}

__global__ void k_fin(int layer) {  // finalize layer BN stats, re-zero g_stat
    int t = threadIdx.x;
    if (t < HH) {
        float m = g_stat[t] * (1.f / NN);
        float v = g_stat[HH + t] * (1.f / NN) - m * m;
        g_meanL[layer * HH + t] = m;
        g_istdL[layer * HH + t] = rsqrtf(v + EPSV);
        g_stat[t] = 0.f;
        g_stat[HH + t] = 0.f;
    }
}

// per-graph mean pool with fused BN+ReLU (fp16 activations)
__global__ void k_pool(const __half* __restrict__ agg,
                       const float* __restrict__ gamma,
                       const float* __restrict__ beta, int layer) {
    int g = blockIdx.x, c = threadIdx.x;
    int b = g_goff[g], e = g_goff[g + 1];
    float is = g_istdL[layer * HH + c] * gamma[c];
    float sh = beta[c] - g_meanL[layer * HH + c] * is;
    float s = 0.f;
    for (int r = b; r < e; r++) {
        float x = __half2float(agg[(size_t)r * HH + c]);
        s += fmaxf(0.f, fmaf(x, is, sh));
    }
    int n = e - b;
    float cnt = (float)(n > 1 ? n : 1);
    g_pool[g * LH + layer * HH + c] = s / cnt;
}

// ---------------- MLP head ----------------
__global__ void k_lin1(const float* __restrict__ Wl1, const float* __restrict__ bl1) {
    __shared__ float sp[LH];
    int g = blockIdx.x, t = threadIdx.x;
    sp[t]       = g_pool[g * LH + t];
    sp[t + 128] = g_pool[g * LH + t + 128];
    sp[t + 256] = g_pool[g * LH + t + 256];
    __syncthreads();
    float a = bl1[t];
    #pragma unroll 4
    for (int k = 0; k < LH; k++) a = fmaf(sp[k], Wl1[k * HH + t], a);
    g_z[g * HH + t] = a;
}

__global__ void k_bn2() {
    int t = threadIdx.x;
    if (t < HH) {
        float s = 0.f, q = 0.f;
        for (int r = 0; r < GG; r++) {
            float x = g_z[r * HH + t];
            s += x; q += x * x;
        }
        float m = s * (1.f / GG);
        float v = q * (1.f / GG) - m * m;
        g_m2[t] = m;
        g_i2[t] = rsqrtf(v + EPSV);
    }
}

__global__ void k_final(const float* __restrict__ gl, const float* __restrict__ btl,
                        const float* __restrict__ Wl2, const float* __restrict__ bl2,
                        float* __restrict__ out) {
    __shared__ float zr[HH];
    __shared__ float lg[CC];
    __shared__ float s_ls;
    int g = blockIdx.x, t = threadIdx.x;
    float x = g_z[g * HH + t];
    zr[t] = fmaxf(0.f, (x - g_m2[t]) * g_i2[t] * gl[t] + btl[t]);
    __syncthreads();
    if (t < CC) {
        float d = bl2[t];
        #pragma unroll 4
        for (int j = 0; j < HH; j++) d = fmaf(zr[j], Wl2[j * CC + t], d);
        lg[t] = d;
    }
    __syncthreads();
    if (t == 0) {
        float m = lg[0];
        for (int c = 1; c < CC; c++) m = fmaxf(m, lg[c]);
        float se = 0.f;
        for (int c = 0; c < CC; c++) se += expf(lg[c] - m);
        s_ls = m + logf(se);
    }
    __syncthreads();
    if (t < CC) out[g * CC + t] = lg[t] - s_ls;
}

// ---------------- launch (single serial stream) ----------------
extern "C" void kernel_launch(void* const* d_in, const int* in_sizes, int n_in,
                              void* d_out, int out_size) {
    const float* x     = (const float*)d_in[0];
    const int*   ei    = (const int*)d_in[1];     // int32 (JAX x64 disabled)
    const int*   batch = (const int*)d_in[2];
    const float* W1  = (const float*)d_in[3];
    const float* g1  = (const float*)d_in[5];
    const float* bt1 = (const float*)d_in[6];
    const float* Wc  = (const float*)d_in[7];
    const float* gc  = (const float*)d_in[9];
    const float* btc = (const float*)d_in[10];
    const float* Wl1 = (const float*)d_in[11];
    const float* bl1 = (const float*)d_in[12];
    const float* gl  = (const float*)d_in[13];
    const float* btl = (const float*)d_in[14];
    const float* Wl2 = (const float*)d_in[15];
    const float* bl2 = (const float*)d_in[16];
    const int* src = ei;
    const int* dst = ei + EE;

    void *p_hW, *p_aggA, *p_aggB, *p_Wt;
    cudaGetSymbolAddress(&p_hW, g_hW16);
    cudaGetSymbolAddress(&p_aggA, g_aggA);
    cudaGetSymbolAddress(&p_aggB, g_aggB);
    cudaGetSymbolAddress(&p_Wt, g_Wt16);
    __half* hW   = (__half*)p_hW;
    __half* aggA = (__half*)p_aggA;
    __half* aggB = (__half*)p_aggB;
    __half* Wt   = (__half*)p_Wt;

    cudaFuncSetAttribute(k_gemm_h<float>,  cudaFuncAttributeMaxDynamicSharedMemorySize, SMEM_GEMM);
    cudaFuncSetAttribute(k_gemm_h<__half>, cudaFuncAttributeMaxDynamicSharedMemorySize, SMEM_GEMM);

    const int GEMM_GRID = (NN + 127) / 128;
    const int AGG_GRID  = 1480;

    // ---- setup; kernel #4 (profiled) is k_gemm_h ----
    k_count<<<(EE + 255) / 256, 256>>>(dst);          // 1
    s_partial<<<NBLK, 1024>>>(W1, Wc);                // 2 (dinv + W fp16 transpose)
    s_add<<<NBLK, 1024>>>(batch);                     // 3
    k_gemm_h<float><<<GEMM_GRID, 256, SMEM_GEMM>>>(x, Wt, hW, 0, 0, (const float*)0, (const float*)0); // 4 (profiled)
    k_fill<<<(EE + 255) / 256, 256>>>(src, dst);      // 5

    // ---- layer 0 ----
    k_agg<<<AGG_GRID, 256>>>(hW, aggA);
    k_fin<<<1, 128>>>(0);
    k_pool<<<GG, 128>>>(aggA, g1, bt1, 0);

    // ---- layer 1: BN0(aggA) -> aggB ----
    k_gemm_h<__half><<<GEMM_GRID, 256, SMEM_GEMM>>>(aggA, Wt + HH * HH, hW, 1, 0, g1, bt1);
    k_agg<<<AGG_GRID, 256>>>(hW, aggB);
    k_fin<<<1, 128>>>(1);
    k_pool<<<GG, 128>>>(aggB, gc, btc, 1);

    // ---- layer 2: BN1(aggB) -> aggA ----
    k_gemm_h<__half><<<GEMM_GRID, 256, SMEM_GEMM>>>(aggB, Wt + 2 * HH * HH, hW, 1, 1, gc, btc);
    k_agg<<<AGG_GRID, 256>>>(hW, aggA);
    k_fin<<<1, 128>>>(2);
    k_pool<<<GG, 128>>>(aggA, gc + HH, btc + HH, 2);

    // ---- head ----
    k_lin1<<<GG, 128>>>(Wl1, bl1);
    k_bn2<<<1, 128>>>();
    k_final<<<GG, 128>>>(gl, btl, Wl2, bl2, (float*)d_out);
}

// round 16
// speedup vs baseline: 1.1259x; 1.0475x over previous
#include <cuda_runtime.h>
#include <cuda_fp16.h>
#include <cstdint>

#define NN 100000
#define EE 1600000
#define HH 128
#define GG 512
#define CC 10
#define LH 384   // L*H
#define EPSV 1e-5f
#define NBLK 98  // ceil(NN/1024)
#define AGG_GRID 1480

// ---------------- device scratch (no allocations allowed) ----------------
// zero-invariants: g_cnt, g_stat, g_ticket are zero at entry of every call
__device__ __align__(16) __half g_hW16[NN * HH]; // GEMM output, fp16 (dinv-scaled)
__device__ __align__(16) __half g_aggA[NN * HH]; // aggregation ping (fp16)
__device__ __align__(16) __half g_aggB[NN * HH]; // aggregation pong (fp16)
__device__ __align__(16) __half g_Wt16[3 * HH * HH]; // per-layer W, fp16, transposed [n][k]
__device__ float g_dinv[NN];
__device__ int   g_cnt[NN];
__device__ int   g_off[NN + 1];
__device__ int   g_cursor[NN];
__device__ int   g_srcA[EE];
__device__ int   g_bsum[128];
__device__ float g_stat[2 * HH];       // [0:128) sum, [128:256) sumsq
__device__ int   g_ticket;             // last-block-done counter
__device__ float g_meanL[3 * HH];      // per-layer BN stats
__device__ float g_istdL[3 * HH];
__device__ int   g_goff[GG + 1];
__device__ float g_pool[GG * LH];
__device__ float g_z[GG * HH];
__device__ float g_m2[HH];
__device__ float g_i2[HH];

// ---------------- setup kernels ----------------
__global__ void k_count(const int* __restrict__ dst) {
    int e = blockIdx.x * blockDim.x + threadIdx.x;
    if (e < EE) atomicAdd(&g_cnt[dst[e]], 1);
}

// block-local exclusive scan + block sums; writes dinv; ALSO converts+transposes W->fp16
__global__ void s_partial(const float* __restrict__ W1, const float* __restrict__ Wc) {
    __shared__ int wsum[32];
    int tid = threadIdx.x, lane = tid & 31, wid = tid >> 5;
    int idx = blockIdx.x * 1024 + tid;

    // W prep: 3 layers x 16384 elements = 49152 <= 98*1024
    if (idx < 3 * HH * HH) {
        int layer = idx >> 14;
        int e = idx & 16383;
        int k = e >> 7, n = e & 127;     // read coalesced over n
        const float* Wsrc = (layer == 0) ? W1 : (Wc + (layer - 1) * HH * HH);
        g_Wt16[layer * HH * HH + n * HH + k] = __float2half_rn(Wsrc[k * HH + n]);
    }

    int v = (idx < NN) ? g_cnt[idx] : 0;
    if (idx < NN) g_dinv[idx] = rsqrtf((float)(v + 1));
    int x = v;
    #pragma unroll
    for (int o = 1; o < 32; o <<= 1) {
        int y = __shfl_up_sync(0xffffffffu, x, o);
        if (lane >= o) x += y;
    }
    if (lane == 31) wsum[wid] = x;
    __syncthreads();
    if (wid == 0) {
        int w = wsum[lane];
        int xx = w;
        #pragma unroll
        for (int o = 1; o < 32; o <<= 1) {
            int y = __shfl_up_sync(0xffffffffu, xx, o);
            if (lane >= o) xx += y;
        }
        wsum[lane] = xx - w;
    }
    __syncthreads();
    int incl = x + wsum[wid];
    if (idx < NN) g_off[idx] = incl - v;     // block-local exclusive
    if (tid == 1023) g_bsum[blockIdx.x] = incl;
}

// finalize offsets, init cursor, zero g_cnt, graph offsets via boundary scan
__global__ void s_add(const int* __restrict__ batch) {
    __shared__ int sb[128];
    int tid = threadIdx.x;
    if (tid < 128) sb[tid] = (tid < NBLK) ? g_bsum[tid] : 0;
    __syncthreads();
    #pragma unroll
    for (int o = 1; o < 128; o <<= 1) {
        int v = 0;
        if (tid < 128 && tid >= o) v = sb[tid - o];
        __syncthreads();
        if (tid < 128) sb[tid] += v;
        __syncthreads();
    }
    int bpre = (blockIdx.x > 0) ? sb[blockIdx.x - 1] : 0;
    int idx = blockIdx.x * 1024 + tid;
    if (idx < NN) {
        int off = g_off[idx] + bpre;
        g_off[idx] = off;
        g_cursor[idx] = off;
        g_cnt[idx] = 0;                      // restore zero-invariant
        int b = batch[idx];
        int prev = (idx > 0) ? batch[idx - 1] : -1;
        for (int g = prev + 1; g <= b; g++) g_goff[g] = idx;
        if (idx == NN - 1)
            for (int g = b + 1; g <= GG; g++) g_goff[g] = NN;
    }
    if (idx == 0) g_off[NN] = EE;
}

__global__ void k_fill(const int* __restrict__ src, const int* __restrict__ dst) {
    int e = blockIdx.x * blockDim.x + threadIdx.x;
    if (e < EE) {
        int d = dst[e];
        int p = atomicAdd(&g_cursor[d], 1);
        g_srcA[p] = src[e];
    }
}

// ---------------- fp16 tensor-core GEMM (m16n8k16, fp32 accumulate) ----------------
__device__ __forceinline__ void mma_f16(float& c0, float& c1, float& c2, float& c3,
                                        uint32_t a0, uint32_t a1, uint32_t a2, uint32_t a3,
                                        uint32_t b0, uint32_t b1) {
    asm volatile("mma.sync.aligned.m16n8k16.row.col.f32.f16.f16.f32 "
                 "{%0,%1,%2,%3},{%4,%5,%6,%7},{%8,%9},{%0,%1,%2,%3};"
                 : "+f"(c0), "+f"(c1), "+f"(c2), "+f"(c3)
                 : "r"(a0), "r"(a1), "r"(a2), "r"(a3), "r"(b0), "r"(b1));
}

// generic 4-element load -> float4
__device__ __forceinline__ float4 load4(const float* p) { return *(const float4*)p; }
__device__ __forceinline__ float4 load4(const __half* p) {
    uint2 u = *(const uint2*)p;
    float2 lo = __half22float2(*(const __half2*)&u.x);
    float2 hi = __half22float2(*(const __half2*)&u.y);
    return make_float4(lo.x, lo.y, hi.x, hi.y);
}

#define SPAD 136  // smem row stride in halves (68 words): frag banks 4*gid+tig, conflict-free
#define SMEM_SB_BYTES (128 * SPAD * 2)              // 34816
#define SMEM_SA_OFF   SMEM_SB_BYTES
#define SMEM_SC_OFF   (2 * SMEM_SB_BYTES)           // 69632
#define SMEM_GEMM     (SMEM_SC_OFF + 1024)          // 70656 total dynamic smem

// C16[N,128] = fp16( dinv[row] * (relu(BN_layer(A))[N,128] @ W[128,128]) )
template <typename TA>
__global__ __launch_bounds__(256, 2) void k_gemm_h(const TA* __restrict__ A,
                                                   const __half* __restrict__ Wt,
                                                   __half* __restrict__ C16,
                                                   int doBN, int statLayer,
                                                   const float* __restrict__ gamma,
                                                   const float* __restrict__ beta) {
    extern __shared__ __align__(16) char smem[];
    __half (*sB)[SPAD] = (__half(*)[SPAD])(smem);                 // [n][k]
    __half (*sA)[SPAD] = (__half(*)[SPAD])(smem + SMEM_SA_OFF);   // [row][k]
    float* sScale = (float*)(smem + SMEM_SC_OFF);
    float* sShift = sScale + HH;

    int tid = threadIdx.x;
    if (doBN && tid < HH) {
        float is = g_istdL[statLayer * HH + tid] * gamma[tid];
        sScale[tid] = is;
        sShift[tid] = beta[tid] - g_meanL[statLayer * HH + tid] * is;
    }

    // stage full W slice from fp16 pre-transposed Wt (vectorized, coalesced)
    #pragma unroll
    for (int i = 0; i < 16; i++) {
        int idx = i * 256 + tid;          // 4096 packs of 4 k-values
        int n  = idx >> 5;                // 0..127
        int k0 = (idx & 31) * 4;          // 0..124
        *(uint2*)&sB[n][k0] = *(const uint2*)(Wt + (size_t)n * HH + k0);
    }
    __syncthreads();   // orders sScale/sShift writes before A-staging reads

    int rowBase = blockIdx.x * 128;

    // stage full A tile [128 x 128] (BN+ReLU fused), fp16
    #pragma unroll
    for (int i = 0; i < 16; i++) {
        int v = i * 256 + tid;
        int row = v & 127;
        int k0 = (v >> 7) * 4;            // 0..124
        int gr = rowBase + row;
        float4 a4 = make_float4(0.f, 0.f, 0.f, 0.f);
        if (gr < NN) a4 = load4(A + (size_t)gr * HH + k0);
        if (doBN) {
            a4.x = fmaxf(0.f, fmaf(a4.x, sScale[k0], sShift[k0]));
            a4.y = fmaxf(0.f, fmaf(a4.y, sScale[k0 + 1], sShift[k0 + 1]));
            a4.z = fmaxf(0.f, fmaf(a4.z, sScale[k0 + 2], sShift[k0 + 2]));
            a4.w = fmaxf(0.f, fmaf(a4.w, sScale[k0 + 3], sShift[k0 + 3]));
        }
        __half2 h01 = __floats2half2_rn(a4.x, a4.y);
        __half2 h23 = __floats2half2_rn(a4.z, a4.w);
        uint2 pk = make_uint2(*(uint32_t*)&h01, *(uint32_t*)&h23);
        *(uint2*)&sA[row][k0] = pk;
    }
    __syncthreads();

    int lane = tid & 31, wid = tid >> 5;
    int gid = lane >> 2, tig = lane & 3;
    int warp_m = wid & 3, warp_n = wid >> 2;     // 4 x 2 warp grid
    int mrow = warp_m * 32;
    int ncol0 = warp_n * 64;

    float acc[2][8][4];
    #pragma unroll
    for (int mt = 0; mt < 2; mt++)
        #pragma unroll
        for (int nt = 0; nt < 8; nt++)
            #pragma unroll
            for (int r = 0; r < 4; r++) acc[mt][nt][r] = 0.f;

    #pragma unroll
    for (int ks = 0; ks < 8; ks++) {
        int kg = ks * 16;
        uint32_t a[2][4];
        #pragma unroll
        for (int mt = 0; mt < 2; mt++) {
            int m0 = mrow + mt * 16 + gid;
            a[mt][0] = *(const uint32_t*)&sA[m0][kg + 2 * tig];
            a[mt][1] = *(const uint32_t*)&sA[m0 + 8][kg + 2 * tig];
            a[mt][2] = *(const uint32_t*)&sA[m0][kg + 2 * tig + 8];
            a[mt][3] = *(const uint32_t*)&sA[m0 + 8][kg + 2 * tig + 8];
        }
        #pragma unroll
        for (int nt = 0; nt < 8; nt++) {
            int nc = ncol0 + nt * 8 + gid;
            uint32_t b0 = *(const uint32_t*)&sB[nc][kg + 2 * tig];
            uint32_t b1 = *(const uint32_t*)&sB[nc][kg + 2 * tig + 8];
            #pragma unroll
            for (int mt = 0; mt < 2; mt++) {
                float* c = acc[mt][nt];
                mma_f16(c[0], c[1], c[2], c[3],
                        a[mt][0], a[mt][1], a[mt][2], a[mt][3], b0, b1);
            }
        }
    }

    // epilogue: scale by dinv[row], convert fp16, write
    #pragma unroll
    for (int mt = 0; mt < 2; mt++) {
        int r0 = rowBase + mrow + mt * 16 + gid;
        int r1 = r0 + 8;
        float dv0 = (r0 < NN) ? g_dinv[r0] : 0.f;
        float dv1 = (r1 < NN) ? g_dinv[r1] : 0.f;
        #pragma unroll
        for (int nt = 0; nt < 8; nt++) {
            int c = ncol0 + nt * 8 + 2 * tig;
            float* a2 = acc[mt][nt];
            if (r0 < NN) *(__half2*)(C16 + (size_t)r0 * HH + c) = __floats2half2_rn(a2[0] * dv0, a2[1] * dv0);
            if (r1 < NN) *(__half2*)(C16 + (size_t)r1 * HH + c) = __floats2half2_rn(a2[2] * dv1, a2[3] * dv1);
        }
    }
}

// ---------------- aggregation: pipelined CSR gather + fused BN stat FINALIZE ----------------
// out[d] = dinv[d] * ( sum_{s in N(d)} hs[s] + hs[d] );  last block finalizes BN stats.
#define AGG_GATHER(dst4, sidx) \
    { uint2 _r = *(const uint2*)(hw + (size_t)(sidx) * HH + col); dst4 = _r; }
#define AGG_ACC(r) \
    { float2 _a = __half22float2(*(__half2*)&(r).x); \
      float2 _b = __half22float2(*(__half2*)&(r).y); \
      ax += _a.x; ay += _a.y; az += _b.x; aw += _b.y; }

__global__ __launch_bounds__(256) void k_agg(const __half* __restrict__ hw,
                                             __half* __restrict__ out, int layer) {
    __shared__ float s_sum[HH], s_sq[HH];
    __shared__ int sLast;
    int tid = threadIdx.x;
    if (tid < HH) { s_sum[tid] = 0.f; s_sq[tid] = 0.f; }
    __syncthreads();
    int lane = tid & 31;
    int col = lane * 4;
    int gw = (blockIdx.x * blockDim.x + tid) >> 5;
    int nw = (gridDim.x * blockDim.x) >> 5;
    float lsx = 0.f, lsy = 0.f, lsz = 0.f, lsw = 0.f;
    float lqx = 0.f, lqy = 0.f, lqz = 0.f, lqw = 0.f;
    for (int node = gw; node < NN; node += nw) {
        uint2 rv;
        AGG_GATHER(rv, node);
        float2 f0 = __half22float2(*(__half2*)&rv.x);
        float2 f1 = __half22float2(*(__half2*)&rv.y);
        float ax = f0.x, ay = f0.y, az = f1.x, aw = f1.y;
        int e0 = __ldg(&g_off[node]), e1 = __ldg(&g_off[node + 1]);
        int deg = e1 - e0;
        int nf = deg >> 2;
        if (nf >= 2) {
            int s0 = __ldg(&g_srcA[e0]),     s1 = __ldg(&g_srcA[e0 + 1]);
            int s2 = __ldg(&g_srcA[e0 + 2]), s3 = __ldg(&g_srcA[e0 + 3]);
            uint2 p0, p1, p2, p3;
            AGG_GATHER(p0, s0); AGG_GATHER(p1, s1); AGG_GATHER(p2, s2); AGG_GATHER(p3, s3);
            int t0 = __ldg(&g_srcA[e0 + 4]), t1 = __ldg(&g_srcA[e0 + 5]);
            int t2 = __ldg(&g_srcA[e0 + 6]), t3 = __ldg(&g_srcA[e0 + 7]);
            int e = e0 + 8;
            int iters = nf - 2;
            while (iters > 0) {
                uint2 q0, q1, q2, q3;
                AGG_GATHER(q0, t0); AGG_GATHER(q1, t1); AGG_GATHER(q2, t2); AGG_GATHER(q3, t3);
                t0 = __ldg(&g_srcA[e]);     t1 = __ldg(&g_srcA[e + 1]);
                t2 = __ldg(&g_srcA[e + 2]); t3 = __ldg(&g_srcA[e + 3]);
                AGG_ACC(p0); AGG_ACC(p1); AGG_ACC(p2); AGG_ACC(p3);
                p0 = q0; p1 = q1; p2 = q2; p3 = q3;
                e += 4; iters--;
            }
            uint2 q0, q1, q2, q3;
            AGG_GATHER(q0, t0); AGG_GATHER(q1, t1); AGG_GATHER(q2, t2); AGG_GATHER(q3, t3);
            AGG_ACC(p0); AGG_ACC(p1); AGG_ACC(p2); AGG_ACC(p3);
            AGG_ACC(q0); AGG_ACC(q1); AGG_ACC(q2); AGG_ACC(q3);
        } else if (nf == 1) {
            int s0 = __ldg(&g_srcA[e0]),     s1 = __ldg(&g_srcA[e0 + 1]);
            int s2 = __ldg(&g_srcA[e0 + 2]), s3 = __ldg(&g_srcA[e0 + 3]);
            uint2 p0, p1, p2, p3;
            AGG_GATHER(p0, s0); AGG_GATHER(p1, s1); AGG_GATHER(p2, s2); AGG_GATHER(p3, s3);
            AGG_ACC(p0); AGG_ACC(p1); AGG_ACC(p2); AGG_ACC(p3);
        }
        for (int e = e0 + (nf << 2); e < e1; e++) {
            int s0 = __ldg(&g_srcA[e]);
            uint2 r0;
            AGG_GATHER(r0, s0);
            AGG_ACC(r0);
        }
        float dv = g_dinv[node];
        ax *= dv; ay *= dv; az *= dv; aw *= dv;
        __half2 o01 = __floats2half2_rn(ax, ay);
        __half2 o23 = __floats2half2_rn(az, aw);
        uint2 ov = make_uint2(*(uint32_t*)&o01, *(uint32_t*)&o23);
        *(uint2*)(out + (size_t)node * HH + col) = ov;
        lsx += ax; lsy += ay; lsz += az; lsw += aw;
        lqx += ax * ax; lqy += ay * ay; lqz += az * az; lqw += aw * aw;
    }
    atomicAdd(&s_sum[col], lsx);     atomicAdd(&s_sum[col + 1], lsy);
    atomicAdd(&s_sum[col + 2], lsz); atomicAdd(&s_sum[col + 3], lsw);
    atomicAdd(&s_sq[col], lqx);      atomicAdd(&s_sq[col + 1], lqy);
    atomicAdd(&s_sq[col + 2], lqz);  atomicAdd(&s_sq[col + 3], lqw);
    __syncthreads();
    if (tid < HH) {
        atomicAdd(&g_stat[tid], s_sum[tid]);
        atomicAdd(&g_stat[HH + tid], s_sq[tid]);
    }
    __threadfence();
    __syncthreads();
    if (tid == 0) {
        int p = atomicAdd(&g_ticket, 1);
        sLast = (p == (int)gridDim.x - 1);
    }
    __syncthreads();
    if (sLast) {                      // last block: finalize BN stats, restore invariants
        if (tid < HH) {
            float m = g_stat[tid] * (1.f / NN);
            float v = g_stat[HH + tid] * (1.f / NN) - m * m;
            g_meanL[layer * HH + tid] = m;
            g_istdL[layer * HH + tid] = rsqrtf(v + EPSV);
            g_stat[tid] = 0.f;
            g_stat[HH + tid] = 0.f;
        }
        if (tid == 0) g_ticket = 0;
    }
}

// per-graph mean pool with fused BN+ReLU (fp16 activations)
__global__ void k_pool(const __half* __restrict__ agg,
                       const float* __restrict__ gamma,
                       const float* __restrict__ beta, int layer) {
    int g = blockIdx.x, c = threadIdx.x;
    int b = g_goff[g], e = g_goff[g + 1];
    float is = g_istdL[layer * HH + c] * gamma[c];
    float sh = beta[c] - g_meanL[layer * HH + c] * is;
    float s = 0.f;
    for (int r = b; r < e; r++) {
        float x = __half2float(agg[(size_t)r * HH + c]);
        s += fmaxf(0.f, fmaf(x, is, sh));
    }
    int n = e - b;
    float cnt = (float)(n > 1 ? n : 1);
    g_pool[g * LH + layer * HH + c] = s / cnt;
}

// ---------------- MLP head: lin1 with fused BN2 stat accumulation/finalize ----------------
__global__ void k_lin1(const float* __restrict__ Wl1, const float* __restrict__ bl1) {
    __shared__ float sp[LH];
    __shared__ int sLast;
    int g = blockIdx.x, t = threadIdx.x;
    sp[t]       = g_pool[g * LH + t];
    sp[t + 128] = g_pool[g * LH + t + 128];
    sp[t + 256] = g_pool[g * LH + t + 256];
    __syncthreads();
    float a = bl1[t];
    #pragma unroll 4
    for (int k = 0; k < LH; k++) a = fmaf(sp[k], Wl1[k * HH + t], a);
    g_z[g * HH + t] = a;
    atomicAdd(&g_stat[t], a);
    atomicAdd(&g_stat[HH + t], a * a);
    __threadfence();
    __syncthreads();
    if (t == 0) {
        int p = atomicAdd(&g_ticket, 1);
        sLast = (p == GG - 1);
    }
    __syncthreads();
    if (sLast) {
        float m = g_stat[t] * (1.f / GG);
        float v = g_stat[HH + t] * (1.f / GG) - m * m;
        g_m2[t] = m;
        g_i2[t] = rsqrtf(v + EPSV);
        g_stat[t] = 0.f;
        g_stat[HH + t] = 0.f;
        if (t == 0) g_ticket = 0;
    }
}

__global__ void k_final(const float* __restrict__ gl, const float* __restrict__ btl,
                        const float* __restrict__ Wl2, const float* __restrict__ bl2,
                        float* __restrict__ out) {
    __shared__ float zr[HH];
    __shared__ float lg[CC];
    __shared__ float s_ls;
    int g = blockIdx.x, t = threadIdx.x;
    float x = g_z[g * HH + t];
    zr[t] = fmaxf(0.f, (x - g_m2[t]) * g_i2[t] * gl[t] + btl[t]);
    __syncthreads();
    if (t < CC) {
        float d = bl2[t];
        #pragma unroll 4
        for (int j = 0; j < HH; j++) d = fmaf(zr[j], Wl2[j * CC + t], d);
        lg[t] = d;
    }
    __syncthreads();
    if (t == 0) {
        float m = lg[0];
        for (int c = 1; c < CC; c++) m = fmaxf(m, lg[c]);
        float se = 0.f;
        for (int c = 0; c < CC; c++) se += expf(lg[c] - m);
        s_ls = m + logf(se);
    }
    __syncthreads();
    if (t < CC) out[g * CC + t] = lg[t] - s_ls;
}

// ---------------- launch ----------------
extern "C" void kernel_launch(void* const* d_in, const int* in_sizes, int n_in,
                              void* d_out, int out_size) {
    const float* x     = (const float*)d_in[0];
    const int*   ei    = (const int*)d_in[1];     // int32 (JAX x64 disabled)
    const int*   batch = (const int*)d_in[2];
    const float* W1  = (const float*)d_in[3];
    const float* g1  = (const float*)d_in[5];
    const float* bt1 = (const float*)d_in[6];
    const float* Wc  = (const float*)d_in[7];
    const float* gc  = (const float*)d_in[9];
    const float* btc = (const float*)d_in[10];
    const float* Wl1 = (const float*)d_in[11];
    const float* bl1 = (const float*)d_in[12];
    const float* gl  = (const float*)d_in[13];
    const float* btl = (const float*)d_in[14];
    const float* Wl2 = (const float*)d_in[15];
    const float* bl2 = (const float*)d_in[16];
    const int* src = ei;
    const int* dst = ei + EE;

    void *p_hW, *p_aggA, *p_aggB, *p_Wt;
    cudaGetSymbolAddress(&p_hW, g_hW16);
    cudaGetSymbolAddress(&p_aggA, g_aggA);
    cudaGetSymbolAddress(&p_aggB, g_aggB);
    cudaGetSymbolAddress(&p_Wt, g_Wt16);
    __half* hW   = (__half*)p_hW;
    __half* aggA = (__half*)p_aggA;
    __half* aggB = (__half*)p_aggB;
    __half* Wt   = (__half*)p_Wt;

    cudaFuncSetAttribute(k_gemm_h<float>,  cudaFuncAttributeMaxDynamicSharedMemorySize, SMEM_GEMM);
    cudaFuncSetAttribute(k_gemm_h<__half>, cudaFuncAttributeMaxDynamicSharedMemorySize, SMEM_GEMM);

    // persistent side stream + events (resource handles only)
    static cudaStream_t s2 = 0;
    static cudaEvent_t eS = 0, eF = 0;
    if (!s2) {
        cudaStreamCreateWithFlags(&s2, cudaStreamNonBlocking);
        cudaEventCreateWithFlags(&eS, cudaEventDisableTiming);
        cudaEventCreateWithFlags(&eF, cudaEventDisableTiming);
    }

    const int GEMM_GRID = (NN + 127) / 128;

    // ---- setup; kernel #4 (profiled) is k_gemm_h; k_fill overlaps GEMM0 on s2 ----
    k_count<<<(EE + 255) / 256, 256>>>(dst);          // 1
    s_partial<<<NBLK, 1024>>>(W1, Wc);                // 2 (dinv + W fp16 transpose)
    s_add<<<NBLK, 1024>>>(batch);                     // 3
    cudaEventRecord(eS, 0);
    k_gemm_h<float><<<GEMM_GRID, 256, SMEM_GEMM>>>(x, Wt, hW, 0, 0, (const float*)0, (const float*)0); // 4 (profiled)
    cudaStreamWaitEvent(s2, eS, 0);
    k_fill<<<(EE + 255) / 256, 256, 0, s2>>>(src, dst);  // 5 (s2, concurrent w/ GEMM0)
    cudaEventRecord(eF, s2);
    cudaStreamWaitEvent(0, eF, 0);

    // ---- layer 0 (agg finalizes BN stats in-kernel) ----
    k_agg<<<AGG_GRID, 256>>>(hW, aggA, 0);
    k_pool<<<GG, 128>>>(aggA, g1, bt1, 0);

    // ---- layer 1: BN0(aggA) -> aggB ----
    k_gemm_h<__half><<<GEMM_GRID, 256, SMEM_GEMM>>>(aggA, Wt + HH * HH, hW, 1, 0, g1, bt1);
    k_agg<<<AGG_GRID, 256>>>(hW, aggB, 1);
    k_pool<<<GG, 128>>>(aggB, gc, btc, 1);

    // ---- layer 2: BN1(aggB) -> aggA ----
    k_gemm_h<__half><<<GEMM_GRID, 256, SMEM_GEMM>>>(aggB, Wt + 2 * HH * HH, hW, 1, 1, gc, btc);
    k_agg<<<AGG_GRID, 256>>>(hW, aggA, 2);
    k_pool<<<GG, 128>>>(aggA, gc + HH, btc + HH, 2);

    // ---- head (lin1 fuses BN2 stats; bn2 kernel deleted) ----
    k_lin1<<<GG, 128>>>(Wl1, bl1);
    k_final<<<GG, 128>>>(gl, btl, Wl2, bl2, (float*)d_out);
}

// round 17
// speedup vs baseline: 1.1387x; 1.0113x over previous
#include <cuda_runtime.h>
#include <cuda_fp16.h>
#include <cstdint>

#define NN 100000
#define EE 1600000
#define HH 128
#define GG 512
#define CC 10
#define LH 384   // L*H
#define EPSV 1e-5f
#define NBLK 98  // ceil(NN/1024)
#define AGG_GRID 1480

// ---------------- device scratch (no allocations allowed) ----------------
// zero-invariants: g_cnt, g_stat, g_ticket are zero at entry of every call
__device__ __align__(16) __half g_hW16[NN * HH]; // GEMM output, fp16 (dinv-scaled)
__device__ __align__(16) __half g_aggA[NN * HH]; // aggregation ping (fp16)
__device__ __align__(16) __half g_aggB[NN * HH]; // aggregation pong (fp16)
__device__ __align__(16) __half g_Wt16[3 * HH * HH]; // per-layer W, fp16, transposed [n][k]
__device__ float g_dinv[NN];
__device__ int   g_cnt[NN];
__device__ int   g_off[NN + 1];
__device__ int   g_cursor[NN];
__device__ int   g_srcA[EE];
__device__ int   g_bsum[128];
__device__ float g_stat[2 * HH];       // [0:128) sum, [128:256) sumsq
__device__ int   g_ticket;             // last-block-done counter
__device__ float g_meanL[3 * HH];      // per-layer BN stats
__device__ float g_istdL[3 * HH];
__device__ int   g_goff[GG + 1];
__device__ float g_pool[GG * LH];
__device__ float g_z[GG * HH];
__device__ float g_m2[HH];
__device__ float g_i2[HH];

// ---------------- setup kernels ----------------
__global__ void k_count(const int* __restrict__ dst) {
    int e = blockIdx.x * blockDim.x + threadIdx.x;
    if (e < EE) atomicAdd(&g_cnt[dst[e]], 1);
}

// block-local exclusive scan + block sums; writes dinv; ALSO converts+transposes W->fp16
__global__ void s_partial(const float* __restrict__ W1, const float* __restrict__ Wc) {
    __shared__ int wsum[32];
    int tid = threadIdx.x, lane = tid & 31, wid = tid >> 5;
    int idx = blockIdx.x * 1024 + tid;

    // W prep: 3 layers x 16384 elements = 49152 <= 98*1024
    if (idx < 3 * HH * HH) {
        int layer = idx >> 14;
        int e = idx & 16383;
        int k = e >> 7, n = e & 127;     // read coalesced over n
        const float* Wsrc = (layer == 0) ? W1 : (Wc + (layer - 1) * HH * HH);
        g_Wt16[layer * HH * HH + n * HH + k] = __float2half_rn(Wsrc[k * HH + n]);
    }

    int v = (idx < NN) ? g_cnt[idx] : 0;
    if (idx < NN) g_dinv[idx] = rsqrtf((float)(v + 1));
    int x = v;
    #pragma unroll
    for (int o = 1; o < 32; o <<= 1) {
        int y = __shfl_up_sync(0xffffffffu, x, o);
        if (lane >= o) x += y;
    }
    if (lane == 31) wsum[wid] = x;
    __syncthreads();
    if (wid == 0) {
        int w = wsum[lane];
        int xx = w;
        #pragma unroll
        for (int o = 1; o < 32; o <<= 1) {
            int y = __shfl_up_sync(0xffffffffu, xx, o);
            if (lane >= o) xx += y;
        }
        wsum[lane] = xx - w;
    }
    __syncthreads();
    int incl = x + wsum[wid];
    if (idx < NN) g_off[idx] = incl - v;     // block-local exclusive
    if (tid == 1023) g_bsum[blockIdx.x] = incl;
}

// finalize offsets, init cursor, zero g_cnt, graph offsets via boundary scan
__global__ void s_add(const int* __restrict__ batch) {
    __shared__ int sb[128];
    int tid = threadIdx.x;
    if (tid < 128) sb[tid] = (tid < NBLK) ? g_bsum[tid] : 0;
    __syncthreads();
    #pragma unroll
    for (int o = 1; o < 128; o <<= 1) {
        int v = 0;
        if (tid < 128 && tid >= o) v = sb[tid - o];
        __syncthreads();
        if (tid < 128) sb[tid] += v;
        __syncthreads();
    }
    int bpre = (blockIdx.x > 0) ? sb[blockIdx.x - 1] : 0;
    int idx = blockIdx.x * 1024 + tid;
    if (idx < NN) {
        int off = g_off[idx] + bpre;
        g_off[idx] = off;
        g_cursor[idx] = off;
        g_cnt[idx] = 0;                      // restore zero-invariant
        int b = batch[idx];
        int prev = (idx > 0) ? batch[idx - 1] : -1;
        for (int g = prev + 1; g <= b; g++) g_goff[g] = idx;
        if (idx == NN - 1)
            for (int g = b + 1; g <= GG; g++) g_goff[g] = NN;
    }
    if (idx == 0) g_off[NN] = EE;
}

__global__ void k_fill(const int* __restrict__ src, const int* __restrict__ dst) {
    int e = blockIdx.x * blockDim.x + threadIdx.x;
    if (e < EE) {
        int d = dst[e];
        int p = atomicAdd(&g_cursor[d], 1);
        g_srcA[p] = src[e];
    }
}

// ---------------- fp16 tensor-core GEMM (m16n8k16, fp32 accumulate) ----------------
__device__ __forceinline__ void mma_f16(float& c0, float& c1, float& c2, float& c3,
                                        uint32_t a0, uint32_t a1, uint32_t a2, uint32_t a3,
                                        uint32_t b0, uint32_t b1) {
    asm volatile("mma.sync.aligned.m16n8k16.row.col.f32.f16.f16.f32 "
                 "{%0,%1,%2,%3},{%4,%5,%6,%7},{%8,%9},{%0,%1,%2,%3};"
                 : "+f"(c0), "+f"(c1), "+f"(c2), "+f"(c3)
                 : "r"(a0), "r"(a1), "r"(a2), "r"(a3), "r"(b0), "r"(b1));
}

// generic 4-element load -> float4
__device__ __forceinline__ float4 load4(const float* p) { return *(const float4*)p; }
__device__ __forceinline__ float4 load4(const __half* p) {
    uint2 u = *(const uint2*)p;
    float2 lo = __half22float2(*(const __half2*)&u.x);
    float2 hi = __half22float2(*(const __half2*)&u.y);
    return make_float4(lo.x, lo.y, hi.x, hi.y);
}

#define SPAD 136  // smem row stride in halves (68 words): frag banks 4*gid+tig, conflict-free
#define SMEM_SB_BYTES (128 * SPAD * 2)              // 34816
#define SMEM_SA_OFF   SMEM_SB_BYTES
#define SMEM_SC_OFF   (2 * SMEM_SB_BYTES)           // 69632
#define SMEM_GEMM     (SMEM_SC_OFF + 1024)          // 70656 total dynamic smem

// C16[N,128] = fp16( dinv[row] * (relu(BN_layer(A))[N,128] @ W[128,128]) )
template <typename TA>
__global__ __launch_bounds__(256, 2) void k_gemm_h(const TA* __restrict__ A,
                                                   const __half* __restrict__ Wt,
                                                   __half* __restrict__ C16,
                                                   int doBN, int statLayer,
                                                   const float* __restrict__ gamma,
                                                   const float* __restrict__ beta) {
    extern __shared__ __align__(16) char smem[];
    __half (*sB)[SPAD] = (__half(*)[SPAD])(smem);                 // [n][k]
    __half (*sA)[SPAD] = (__half(*)[SPAD])(smem + SMEM_SA_OFF);   // [row][k]
    float* sScale = (float*)(smem + SMEM_SC_OFF);
    float* sShift = sScale + HH;

    int tid = threadIdx.x;
    if (doBN && tid < HH) {
        float is = g_istdL[statLayer * HH + tid] * gamma[tid];
        sScale[tid] = is;
        sShift[tid] = beta[tid] - g_meanL[statLayer * HH + tid] * is;
    }

    // stage full W slice from fp16 pre-transposed Wt (vectorized, coalesced)
    #pragma unroll
    for (int i = 0; i < 16; i++) {
        int idx = i * 256 + tid;          // 4096 packs of 4 k-values
        int n  = idx >> 5;                // 0..127
        int k0 = (idx & 31) * 4;          // 0..124
        *(uint2*)&sB[n][k0] = *(const uint2*)(Wt + (size_t)n * HH + k0);
    }
    __syncthreads();   // orders sScale/sShift writes before A-staging reads

    int rowBase = blockIdx.x * 128;

    // stage full A tile [128 x 128] (BN+ReLU fused), fp16
    #pragma unroll
    for (int i = 0; i < 16; i++) {
        int v = i * 256 + tid;
        int row = v & 127;
        int k0 = (v >> 7) * 4;            // 0..124
        int gr = rowBase + row;
        float4 a4 = make_float4(0.f, 0.f, 0.f, 0.f);
        if (gr < NN) a4 = load4(A + (size_t)gr * HH + k0);
        if (doBN) {
            a4.x = fmaxf(0.f, fmaf(a4.x, sScale[k0], sShift[k0]));
            a4.y = fmaxf(0.f, fmaf(a4.y, sScale[k0 + 1], sShift[k0 + 1]));
            a4.z = fmaxf(0.f, fmaf(a4.z, sScale[k0 + 2], sShift[k0 + 2]));
            a4.w = fmaxf(0.f, fmaf(a4.w, sScale[k0 + 3], sShift[k0 + 3]));
        }
        __half2 h01 = __floats2half2_rn(a4.x, a4.y);
        __half2 h23 = __floats2half2_rn(a4.z, a4.w);
        uint2 pk = make_uint2(*(uint32_t*)&h01, *(uint32_t*)&h23);
        *(uint2*)&sA[row][k0] = pk;
    }
    __syncthreads();

    int lane = tid & 31, wid = tid >> 5;
    int gid = lane >> 2, tig = lane & 3;
    int warp_m = wid & 3, warp_n = wid >> 2;     // 4 x 2 warp grid
    int mrow = warp_m * 32;
    int ncol0 = warp_n * 64;

    float acc[2][8][4];
    #pragma unroll
    for (int mt = 0; mt < 2; mt++)
        #pragma unroll
        for (int nt = 0; nt < 8; nt++)
            #pragma unroll
            for (int r = 0; r < 4; r++) acc[mt][nt][r] = 0.f;

    #pragma unroll
    for (int ks = 0; ks < 8; ks++) {
        int kg = ks * 16;
        uint32_t a[2][4];
        #pragma unroll
        for (int mt = 0; mt < 2; mt++) {
            int m0 = mrow + mt * 16 + gid;
            a[mt][0] = *(const uint32_t*)&sA[m0][kg + 2 * tig];
            a[mt][1] = *(const uint32_t*)&sA[m0 + 8][kg + 2 * tig];
            a[mt][2] = *(const uint32_t*)&sA[m0][kg + 2 * tig + 8];
            a[mt][3] = *(const uint32_t*)&sA[m0 + 8][kg + 2 * tig + 8];
        }
        #pragma unroll
        for (int nt = 0; nt < 8; nt++) {
            int nc = ncol0 + nt * 8 + gid;
            uint32_t b0 = *(const uint32_t*)&sB[nc][kg + 2 * tig];
            uint32_t b1 = *(const uint32_t*)&sB[nc][kg + 2 * tig + 8];
            #pragma unroll
            for (int mt = 0; mt < 2; mt++) {
                float* c = acc[mt][nt];
                mma_f16(c[0], c[1], c[2], c[3],
                        a[mt][0], a[mt][1], a[mt][2], a[mt][3], b0, b1);
            }
        }
    }

    // epilogue: scale by dinv[row], convert fp16, write
    #pragma unroll
    for (int mt = 0; mt < 2; mt++) {
        int r0 = rowBase + mrow + mt * 16 + gid;
        int r1 = r0 + 8;
        float dv0 = (r0 < NN) ? g_dinv[r0] : 0.f;
        float dv1 = (r1 < NN) ? g_dinv[r1] : 0.f;
        #pragma unroll
        for (int nt = 0; nt < 8; nt++) {
            int c = ncol0 + nt * 8 + 2 * tig;
            float* a2 = acc[mt][nt];
            if (r0 < NN) *(__half2*)(C16 + (size_t)r0 * HH + c) = __floats2half2_rn(a2[0] * dv0, a2[1] * dv0);
            if (r1 < NN) *(__half2*)(C16 + (size_t)r1 * HH + c) = __floats2half2_rn(a2[2] * dv1, a2[3] * dv1);
        }
    }
}

// ---------------- aggregation: pipelined CSR gather + fused BN stat FINALIZE ----------------
#define AGG_GATHER(dst4, sidx) \
    { uint2 _r = *(const uint2*)(hw + (size_t)(sidx) * HH + col); dst4 = _r; }
#define AGG_ACC(r) \
    { float2 _a = __half22float2(*(__half2*)&(r).x); \
      float2 _b = __half22float2(*(__half2*)&(r).y); \
      ax += _a.x; ay += _a.y; az += _b.x; aw += _b.y; }

__global__ __launch_bounds__(256) void k_agg(const __half* __restrict__ hw,
                                             __half* __restrict__ out, int layer) {
    __shared__ float s_sum[HH], s_sq[HH];
    __shared__ int sLast;
    int tid = threadIdx.x;
    if (tid < HH) { s_sum[tid] = 0.f; s_sq[tid] = 0.f; }
    __syncthreads();
    int lane = tid & 31;
    int col = lane * 4;
    int gw = (blockIdx.x * blockDim.x + tid) >> 5;
    int nw = (gridDim.x * blockDim.x) >> 5;
    float lsx = 0.f, lsy = 0.f, lsz = 0.f, lsw = 0.f;
    float lqx = 0.f, lqy = 0.f, lqz = 0.f, lqw = 0.f;
    for (int node = gw; node < NN; node += nw) {
        uint2 rv;
        AGG_GATHER(rv, node);
        float2 f0 = __half22float2(*(__half2*)&rv.x);
        float2 f1 = __half22float2(*(__half2*)&rv.y);
        float ax = f0.x, ay = f0.y, az = f1.x, aw = f1.y;
        int e0 = __ldg(&g_off[node]), e1 = __ldg(&g_off[node + 1]);
        int deg = e1 - e0;
        int nf = deg >> 2;
        if (nf >= 2) {
            int s0 = __ldg(&g_srcA[e0]),     s1 = __ldg(&g_srcA[e0 + 1]);
            int s2 = __ldg(&g_srcA[e0 + 2]), s3 = __ldg(&g_srcA[e0 + 3]);
            uint2 p0, p1, p2, p3;
            AGG_GATHER(p0, s0); AGG_GATHER(p1, s1); AGG_GATHER(p2, s2); AGG_GATHER(p3, s3);
            int t0 = __ldg(&g_srcA[e0 + 4]), t1 = __ldg(&g_srcA[e0 + 5]);
            int t2 = __ldg(&g_srcA[e0 + 6]), t3 = __ldg(&g_srcA[e0 + 7]);
            int e = e0 + 8;
            int iters = nf - 2;
            while (iters > 0) {
                uint2 q0, q1, q2, q3;
                AGG_GATHER(q0, t0); AGG_GATHER(q1, t1); AGG_GATHER(q2, t2); AGG_GATHER(q3, t3);
                t0 = __ldg(&g_srcA[e]);     t1 = __ldg(&g_srcA[e + 1]);
                t2 = __ldg(&g_srcA[e + 2]); t3 = __ldg(&g_srcA[e + 3]);
                AGG_ACC(p0); AGG_ACC(p1); AGG_ACC(p2); AGG_ACC(p3);
                p0 = q0; p1 = q1; p2 = q2; p3 = q3;
                e += 4; iters--;
            }
            uint2 q0, q1, q2, q3;
            AGG_GATHER(q0, t0); AGG_GATHER(q1, t1); AGG_GATHER(q2, t2); AGG_GATHER(q3, t3);
            AGG_ACC(p0); AGG_ACC(p1); AGG_ACC(p2); AGG_ACC(p3);
            AGG_ACC(q0); AGG_ACC(q1); AGG_ACC(q2); AGG_ACC(q3);
        } else if (nf == 1) {
            int s0 = __ldg(&g_srcA[e0]),     s1 = __ldg(&g_srcA[e0 + 1]);
            int s2 = __ldg(&g_srcA[e0 + 2]), s3 = __ldg(&g_srcA[e0 + 3]);
            uint2 p0, p1, p2, p3;
            AGG_GATHER(p0, s0); AGG_GATHER(p1, s1); AGG_GATHER(p2, s2); AGG_GATHER(p3, s3);
            AGG_ACC(p0); AGG_ACC(p1); AGG_ACC(p2); AGG_ACC(p3);
        }
        for (int e = e0 + (nf << 2); e < e1; e++) {
            int s0 = __ldg(&g_srcA[e]);
            uint2 r0;
            AGG_GATHER(r0, s0);
            AGG_ACC(r0);
        }
        float dv = g_dinv[node];
        ax *= dv; ay *= dv; az *= dv; aw *= dv;
        __half2 o01 = __floats2half2_rn(ax, ay);
        __half2 o23 = __floats2half2_rn(az, aw);
        uint2 ov = make_uint2(*(uint32_t*)&o01, *(uint32_t*)&o23);
        *(uint2*)(out + (size_t)node * HH + col) = ov;
        lsx += ax; lsy += ay; lsz += az; lsw += aw;
        lqx += ax * ax; lqy += ay * ay; lqz += az * az; lqw += aw * aw;
    }
    atomicAdd(&s_sum[col], lsx);     atomicAdd(&s_sum[col + 1], lsy);
    atomicAdd(&s_sum[col + 2], lsz); atomicAdd(&s_sum[col + 3], lsw);
    atomicAdd(&s_sq[col], lqx);      atomicAdd(&s_sq[col + 1], lqy);
    atomicAdd(&s_sq[col + 2], lqz);  atomicAdd(&s_sq[col + 3], lqw);
    __syncthreads();
    if (tid < HH) {
        atomicAdd(&g_stat[tid], s_sum[tid]);
        atomicAdd(&g_stat[HH + tid], s_sq[tid]);
    }
    __threadfence();
    __syncthreads();
    if (tid == 0) {
        int p = atomicAdd(&g_ticket, 1);
        sLast = (p == (int)gridDim.x - 1);
    }
    __syncthreads();
    if (sLast) {                      // last block: finalize BN stats, restore invariants
        if (tid < HH) {
            float m = g_stat[tid] * (1.f / NN);
            float v = g_stat[HH + tid] * (1.f / NN) - m * m;
            g_meanL[layer * HH + tid] = m;
            g_istdL[layer * HH + tid] = rsqrtf(v + EPSV);
            g_stat[tid] = 0.f;
            g_stat[HH + tid] = 0.f;
        }
        if (tid == 0) g_ticket = 0;
    }
}

// per-graph mean pool with fused BN+ReLU (fp16 activations)
__global__ void k_pool(const __half* __restrict__ agg,
                       const float* __restrict__ gamma,
                       const float* __restrict__ beta, int layer) {
    int g = blockIdx.x, c = threadIdx.x;
    int b = g_goff[g], e = g_goff[g + 1];
    float is = g_istdL[layer * HH + c] * gamma[c];
    float sh = beta[c] - g_meanL[layer * HH + c] * is;
    float s = 0.f;
    for (int r = b; r < e; r++) {
        float x = __half2float(agg[(size_t)r * HH + c]);
        s += fmaxf(0.f, fmaf(x, is, sh));
    }
    int n = e - b;
    float cnt = (float)(n > 1 ? n : 1);
    g_pool[g * LH + layer * HH + c] = s / cnt;
}

// ---------------- MLP head: lin1 with fused BN2 stat accumulation/finalize ----------------
__global__ void k_lin1(const float* __restrict__ Wl1, const float* __restrict__ bl1) {
    __shared__ float sp[LH];
    __shared__ int sLast;
    int g = blockIdx.x, t = threadIdx.x;
    sp[t]       = g_pool[g * LH + t];
    sp[t + 128] = g_pool[g * LH + t + 128];
    sp[t + 256] = g_pool[g * LH + t + 256];
    __syncthreads();
    float a = bl1[t];
    #pragma unroll 4
    for (int k = 0; k < LH; k++) a = fmaf(sp[k], Wl1[k * HH + t], a);
    g_z[g * HH + t] = a;
    atomicAdd(&g_stat[t], a);
    atomicAdd(&g_stat[HH + t], a * a);
    __threadfence();
    __syncthreads();
    if (t == 0) {
        int p = atomicAdd(&g_ticket, 1);
        sLast = (p == GG - 1);
    }
    __syncthreads();
    if (sLast) {
        float m = g_stat[t] * (1.f / GG);
        float v = g_stat[HH + t] * (1.f / GG) - m * m;
        g_m2[t] = m;
        g_i2[t] = rsqrtf(v + EPSV);
        g_stat[t] = 0.f;
        g_stat[HH + t] = 0.f;
        if (t == 0) g_ticket = 0;
    }
}

__global__ void k_final(const float* __restrict__ gl, const float* __restrict__ btl,
                        const float* __restrict__ Wl2, const float* __restrict__ bl2,
                        float* __restrict__ out) {
    __shared__ float zr[HH];
    __shared__ float lg[CC];
    __shared__ float s_ls;
    int g = blockIdx.x, t = threadIdx.x;
    float x = g_z[g * HH + t];
    zr[t] = fmaxf(0.f, (x - g_m2[t]) * g_i2[t] * gl[t] + btl[t]);
    __syncthreads();
    if (t < CC) {
        float d = bl2[t];
        #pragma unroll 4
        for (int j = 0; j < HH; j++) d = fmaf(zr[j], Wl2[j * CC + t], d);
        lg[t] = d;
    }
    __syncthreads();
    if (t == 0) {
        float m = lg[0];
        for (int c = 1; c < CC; c++) m = fmaxf(m, lg[c]);
        float se = 0.f;
        for (int c = 0; c < CC; c++) se += expf(lg[c] - m);
        s_ls = m + logf(se);
    }
    __syncthreads();
    if (t < CC) out[g * CC + t] = lg[t] - s_ls;
}

// ---------------- launch ----------------
extern "C" void kernel_launch(void* const* d_in, const int* in_sizes, int n_in,
                              void* d_out, int out_size) {
    const float* x     = (const float*)d_in[0];
    const int*   ei    = (const int*)d_in[1];     // int32 (JAX x64 disabled)
    const int*   batch = (const int*)d_in[2];
    const float* W1  = (const float*)d_in[3];
    const float* g1  = (const float*)d_in[5];
    const float* bt1 = (const float*)d_in[6];
    const float* Wc  = (const float*)d_in[7];
    const float* gc  = (const float*)d_in[9];
    const float* btc = (const float*)d_in[10];
    const float* Wl1 = (const float*)d_in[11];
    const float* bl1 = (const float*)d_in[12];
    const float* gl  = (const float*)d_in[13];
    const float* btl = (const float*)d_in[14];
    const float* Wl2 = (const float*)d_in[15];
    const float* bl2 = (const float*)d_in[16];
    const int* src = ei;
    const int* dst = ei + EE;

    void *p_hW, *p_aggA, *p_aggB, *p_Wt;
    cudaGetSymbolAddress(&p_hW, g_hW16);
    cudaGetSymbolAddress(&p_aggA, g_aggA);
    cudaGetSymbolAddress(&p_aggB, g_aggB);
    cudaGetSymbolAddress(&p_Wt, g_Wt16);
    __half* hW   = (__half*)p_hW;
    __half* aggA = (__half*)p_aggA;
    __half* aggB = (__half*)p_aggB;
    __half* Wt   = (__half*)p_Wt;

    cudaFuncSetAttribute(k_gemm_h<float>,  cudaFuncAttributeMaxDynamicSharedMemorySize, SMEM_GEMM);
    cudaFuncSetAttribute(k_gemm_h<__half>, cudaFuncAttributeMaxDynamicSharedMemorySize, SMEM_GEMM);

    // persistent side stream + events (resource handles only)
    static cudaStream_t s2 = 0;
    static cudaEvent_t eS = 0, eF = 0, eA0 = 0, eA1 = 0, eA2 = 0, eP0 = 0, ePend = 0;
    if (!s2) {
        cudaStreamCreateWithFlags(&s2, cudaStreamNonBlocking);
        cudaEventCreateWithFlags(&eS,   cudaEventDisableTiming);
        cudaEventCreateWithFlags(&eF,   cudaEventDisableTiming);
        cudaEventCreateWithFlags(&eA0,  cudaEventDisableTiming);
        cudaEventCreateWithFlags(&eA1,  cudaEventDisableTiming);
        cudaEventCreateWithFlags(&eA2,  cudaEventDisableTiming);
        cudaEventCreateWithFlags(&eP0,  cudaEventDisableTiming);
        cudaEventCreateWithFlags(&ePend, cudaEventDisableTiming);
    }

    const int GEMM_GRID = (NN + 127) / 128;

    // ---- setup; kernel #4 (profiled) is k_gemm_h; k_fill overlaps GEMM0 on s2 ----
    k_count<<<(EE + 255) / 256, 256>>>(dst);          // 1
    s_partial<<<NBLK, 1024>>>(W1, Wc);                // 2 (dinv + W fp16 transpose)
    s_add<<<NBLK, 1024>>>(batch);                     // 3
    cudaEventRecord(eS, 0);
    k_gemm_h<float><<<GEMM_GRID, 256, SMEM_GEMM>>>(x, Wt, hW, 0, 0, (const float*)0, (const float*)0); // 4 (profiled)
    cudaStreamWaitEvent(s2, eS, 0);
    k_fill<<<(EE + 255) / 256, 256, 0, s2>>>(src, dst);  // 5 (s2, concurrent w/ GEMM0)
    cudaEventRecord(eF, s2);
    cudaStreamWaitEvent(0, eF, 0);

    // ---- layer 0: agg0 (finalizes BN stats); pool0 on s2 overlapping gemm1 ----
    k_agg<<<AGG_GRID, 256>>>(hW, aggA, 0);
    cudaEventRecord(eA0, 0);
    cudaStreamWaitEvent(s2, eA0, 0);
    k_pool<<<GG, 128, 0, s2>>>(aggA, g1, bt1, 0);
    cudaEventRecord(eP0, s2);

    // ---- layer 1 ----
    k_gemm_h<__half><<<GEMM_GRID, 256, SMEM_GEMM>>>(aggA, Wt + HH * HH, hW, 1, 0, g1, bt1);
    k_agg<<<AGG_GRID, 256>>>(hW, aggB, 1);
    cudaEventRecord(eA1, 0);
    cudaStreamWaitEvent(s2, eA1, 0);
    k_pool<<<GG, 128, 0, s2>>>(aggB, gc, btc, 1);

    // ---- layer 2 (agg2 overwrites aggA -> must wait pool0) ----
    k_gemm_h<__half><<<GEMM_GRID, 256, SMEM_GEMM>>>(aggB, Wt + 2 * HH * HH, hW, 1, 1, gc, btc);
    cudaStreamWaitEvent(0, eP0, 0);
    k_agg<<<AGG_GRID, 256>>>(hW, aggA, 2);
    cudaEventRecord(eA2, 0);
    cudaStreamWaitEvent(s2, eA2, 0);
    k_pool<<<GG, 128, 0, s2>>>(aggA, gc + HH, btc + HH, 2);
    cudaEventRecord(ePend, s2);

    // ---- head (after all pools) ----
    cudaStreamWaitEvent(0, ePend, 0);
    k_lin1<<<GG, 128>>>(Wl1, bl1);
    k_final<<<GG, 128>>>(gl, btl, Wl2, bl2, (float*)d_out);
}